// round 13
// baseline (speedup 1.0000x reference)
#include <cuda_runtime.h>
#include <cuda_bf16.h>
#include <cstdint>
#include <math.h>

#define NN   50000      // nodes
#define NNP  50048      // padded to 128
#define NE   800000     // edges
#define IND  50         // input dim
#define HID  256        // hidden
#define NC   121        // classes
#define PRLS 384        // combined [p(0..127) | r(128..255) | l2(256..383)] row stride
#define K1P  52         // padded K for layer-1
#define NK1  13         // k4 groups for layer-1
#define SW   40         // gemm2 smem row stride (bf16) — conflict-free padding

typedef unsigned long long u64;

// ---------------- scratch (device globals; BSS-zero at load) -------------------
// INVARIANT: g_cnt[] == 0 and g_base == 0 at kernel_launch entry.
__device__ __align__(16) float g_prl [(size_t)NN * PRLS];
__device__ __align__(16) u64 g_w1p[3 * NK1 * HID * 2];
__device__ __align__(16) __nv_bfloat16 g_hhi[(size_t)NNP * HID];
__device__ __align__(16) __nv_bfloat16 g_hlo[(size_t)NNP * HID];
__device__ __align__(16) __nv_bfloat16 g_w2hi[PRLS * HID];
__device__ __align__(16) __nv_bfloat16 g_w2lo[PRLS * HID];
__device__ int g_cnt[NN];
__device__ int g_off[NN];
__device__ int g_cur[NN];
__device__ int g_adj[NE];
__device__ int g_base;

// ---------------- packed fp32x2 helpers --------------------------------------
__device__ __forceinline__ u64 ffma2(u64 a, u64 b, u64 c) {
    u64 d;
    asm("fma.rn.f32x2 %0, %1, %2, %3;" : "=l"(d) : "l"(a), "l"(b), "l"(c));
    return d;
}
__device__ __forceinline__ u64 pk(float a, float b) {
    u64 r; asm("mov.b64 %0, {%1, %2};" : "=l"(r) : "f"(a), "f"(b)); return r;
}
__device__ __forceinline__ float psum(u64 v) {
    float lo, hi; asm("mov.b64 {%0, %1}, %2;" : "=f"(lo), "=f"(hi) : "l"(v));
    return lo + hi;
}

// mma.sync m16n8k16 bf16 (generic PTX — HMMA fallback on plain sm_103)
#define MMA_BF16(D, A, B0, B1)                                               \
    asm volatile("mma.sync.aligned.m16n8k16.row.col.f32.bf16.bf16.f32 "      \
                 "{%0,%1,%2,%3},{%4,%5,%6,%7},{%8,%9},{%0,%1,%2,%3};"        \
                 : "+f"(D[0]), "+f"(D[1]), "+f"(D[2]), "+f"(D[3])            \
                 : "r"(A[0]), "r"(A[1]), "r"(A[2]), "r"(A[3]),               \
                   "r"(B0), "r"(B1))

__device__ __forceinline__ void ldsm4(uint32_t* r, uint32_t addr) {
    asm volatile("ldmatrix.sync.aligned.m8n8.x4.shared.b16 {%0,%1,%2,%3}, [%4];"
                 : "=r"(r[0]), "=r"(r[1]), "=r"(r[2]), "=r"(r[3]) : "r"(addr));
}

// ---------------- launch 1: histogram + weight packing (fused, independent) -----
__global__ __launch_bounds__(256) void histsetup_kernel(
    const int* __restrict__ ei,
    const float* __restrict__ w1l, const float* __restrict__ w1r,
    const float* __restrict__ wl1,
    const float* __restrict__ w2l, const float* __restrict__ w2r,
    const float* __restrict__ wl2)
{
    int t = blockIdx.x * blockDim.x + threadIdx.x;
    if (t < NE) atomicAdd(&g_cnt[ei[NE + t]], 1);
    if (t < 3 * NK1 * HID * 2) {             // pack layer-1 weights [mat][kk][col][pair]
        int m = t / (NK1 * HID * 2), rem = t % (NK1 * HID * 2);
        int kk = rem / (HID * 2), rem2 = rem % (HID * 2);
        int c = rem2 >> 1, h = rem2 & 1;
        int k0 = kk * 4 + h * 2;
        const float* w = (m == 0) ? w1l : (m == 1) ? w1r : wl1;
        float lo = (k0     < IND) ? w[(k0    ) * HID + c] : 0.f;
        float hi = (k0 + 1 < IND) ? w[(k0 + 1) * HID + c] : 0.f;
        g_w1p[t] = pk(lo, hi);
    }
    if (t < PRLS * 32) {                     // layer-2 weights -> bf16 hi/lo [slot][k]
        int slot = t >> 5, k0 = (t & 31) * 8;
        int seg = slot >> 7, idx = slot & 127;
        const float* w = (seg == 0) ? w2l : (seg == 1) ? w2r : wl2;
        union { __nv_bfloat16 b[8]; uint4 v; } H, L;
#pragma unroll
        for (int j = 0; j < 8; j++) {
            float val = (idx < NC) ? w[(k0 + j) * NC + idx] : 0.f;
            __nv_bfloat16 h = __float2bfloat16(val);
            H.b[j] = h;
            L.b[j] = __float2bfloat16(val - __bfloat162float(h));
        }
        *(uint4*)(g_w2hi + (size_t)slot * HID + k0) = H.v;
        *(uint4*)(g_w2lo + (size_t)slot * HID + k0) = L.v;
    }
}

// ---------------- launch 2: order-free CSR offsets ------------------------------
__global__ __launch_bounds__(1024) void offsets_kernel() {
    __shared__ int ws[32];
    __shared__ int sbase;
    int i = blockIdx.x * 1024 + threadIdx.x;
    int lane = threadIdx.x & 31, wid = threadIdx.x >> 5;
    int c = (i < NN) ? g_cnt[i] : 0;
    int v = c;
#pragma unroll
    for (int o = 1; o < 32; o <<= 1) {
        int u = __shfl_up_sync(0xffffffffu, v, o);
        if (lane >= o) v += u;
    }
    if (lane == 31) ws[wid] = v;
    __syncthreads();
    if (wid == 0) {
        int w = ws[lane];
#pragma unroll
        for (int o = 1; o < 32; o <<= 1) {
            int u = __shfl_up_sync(0xffffffffu, w, o);
            if (lane >= o) w += u;
        }
        ws[lane] = w;
    }
    __syncthreads();
    int excl = v - c + (wid ? ws[wid - 1] : 0);
    if (threadIdx.x == 1023) sbase = atomicAdd(&g_base, excl + c);
    __syncthreads();
    if (i < NN) { int o = sbase + excl; g_off[i] = o; g_cur[i] = o; }
}

// ---------------- launch 3: fill adjacency --------------------------------------
__global__ __launch_bounds__(256) void fill_kernel(const int* __restrict__ ei) {
    int e = blockIdx.x * blockDim.x + threadIdx.x;
    if (e >= NE) return;
    int pos = atomicAdd(&g_cur[ei[NE + e]], 1);
    g_adj[pos] = ei[e];
}

// ---------------- launch 4 (PROFILED): gather-mean + layer-1 GEMM + norm + ELU ---
// block = 16 nodes, 256 threads. Phase A: warp-per-node gather of mean(x[nbrs])
// into smem. Phase B: f32x2 GEMM, L2-normalize, ELU, bf16 hi/lo output.
__global__ __launch_bounds__(256, 2) void gemm1_kernel(
    const float* __restrict__ x,
    const float* __restrict__ b1, const float* __restrict__ bl1)
{
    __shared__ __align__(16) float sm[16][K1P];
    __shared__ __align__(16) float sx[16][K1P];
    __shared__ float spart[16][8];

    int c = threadIdx.x;
    int lane = c & 31, warp = c >> 5;
    int row0 = blockIdx.x * 16;

    // Phase A1: load x rows (coalesced) + zero pads
    for (int i = c; i < 16 * K1P; i += 256) {
        int r = i / K1P, cc = i % K1P;
        sx[r][cc] = (cc < IND) ? x[(size_t)(row0 + r) * IND + cc] : 0.f;
    }
    // Phase A2: gather means — each warp handles 2 nodes
#pragma unroll
    for (int s = 0; s < 2; s++) {
        int r = warp * 2 + s;
        int n = row0 + r;
        int b = g_off[n], cnt = g_cnt[n], e2 = b + cnt;
        float inv = 1.f / fmaxf((float)cnt, 1.f);
        bool act = lane < 25;
        float2 a = make_float2(0.f, 0.f);
        int i = b;
        for (; i + 3 < e2; i += 4) {
            int s0 = g_adj[i], s1 = g_adj[i + 1], s2 = g_adj[i + 2], s3 = g_adj[i + 3];
            if (act) {
                float2 v0 = *((const float2*)(x + (size_t)s0 * IND) + lane);
                float2 v1 = *((const float2*)(x + (size_t)s1 * IND) + lane);
                float2 v2 = *((const float2*)(x + (size_t)s2 * IND) + lane);
                float2 v3 = *((const float2*)(x + (size_t)s3 * IND) + lane);
                a.x += (v0.x + v1.x) + (v2.x + v3.x);
                a.y += (v0.y + v1.y) + (v2.y + v3.y);
            }
        }
        for (; i < e2; i++) {
            int s0 = g_adj[i];
            if (act) {
                float2 v0 = *((const float2*)(x + (size_t)s0 * IND) + lane);
                a.x += v0.x; a.y += v0.y;
            }
        }
        if (act) {
            sm[r][2 * lane]     = a.x * inv;
            sm[r][2 * lane + 1] = a.y * inv;
        } else if (lane == 25) {
            sm[r][50] = 0.f; sm[r][51] = 0.f;
        }
    }
    __syncthreads();

    // Phase B: GEMM
    u64 a[16], l[16];
    u64 ib = pk(b1[c], 0.f), il = pk(bl1[c], 0.f);
#pragma unroll
    for (int r = 0; r < 16; r++) { a[r] = ib; l[r] = il; }

    const ulonglong2* wl = (const ulonglong2*)g_w1p + (size_t)(0 * NK1) * HID + c;
    const ulonglong2* wr = (const ulonglong2*)g_w1p + (size_t)(1 * NK1) * HID + c;
    const ulonglong2* wc = (const ulonglong2*)g_w1p + (size_t)(2 * NK1) * HID + c;

#pragma unroll
    for (int kk = 0; kk < NK1; kk++) {
        int k = kk * 4;
        ulonglong2 wL = wl[kk * HID];
        ulonglong2 wR = wr[kk * HID];
        ulonglong2 wC = wc[kk * HID];
#pragma unroll
        for (int r = 0; r < 16; r++) {
            ulonglong2 m2 = *(const ulonglong2*)&sm[r][k];
            ulonglong2 x2 = *(const ulonglong2*)&sx[r][k];
            a[r] = ffma2(m2.x, wL.x, a[r]); a[r] = ffma2(m2.y, wL.y, a[r]);
            a[r] = ffma2(x2.x, wR.x, a[r]); a[r] = ffma2(x2.y, wR.y, a[r]);
            l[r] = ffma2(x2.x, wC.x, l[r]); l[r] = ffma2(x2.y, wC.y, l[r]);
        }
    }

    float sv[16], lv[16];
#pragma unroll
    for (int r = 0; r < 16; r++) { sv[r] = psum(a[r]); lv[r] = psum(l[r]); }

#pragma unroll
    for (int r = 0; r < 16; r++) {
        float v = sv[r] * sv[r];
#pragma unroll
        for (int o = 16; o; o >>= 1) v += __shfl_xor_sync(0xffffffffu, v, o);
        if (lane == 0) spart[r][warp] = v;
    }
    __syncthreads();
#pragma unroll
    for (int r = 0; r < 16; r++) {
        float s = 0.f;
#pragma unroll
        for (int w = 0; w < 8; w++) s += spart[r][w];
        float inv = 1.f / fmaxf(sqrtf(s), 1e-12f);
        float z = sv[r] * inv + lv[r];
        z = (z > 0.f) ? z : expm1f(z);
        __nv_bfloat16 hi = __float2bfloat16(z);
        __nv_bfloat16 lo = __float2bfloat16(z - __bfloat162float(hi));
        size_t idx = (size_t)(row0 + r) * HID + c;
        g_hhi[idx] = hi;
        g_hlo[idx] = lo;
    }
}

// ---------------- launch 5: layer-2 GEMM via mma.sync bf16x3 + ldmatrix -----------
__global__ __launch_bounds__(512, 1) void gemm2_kernel()
{
    extern __shared__ __align__(16) __nv_bfloat16 smem[];
    __nv_bfloat16* shh = smem;                  // [2][128][SW] hi/lo H
    __nv_bfloat16* shw = smem + 2 * 128 * SW;   // [2][192][SW] hi/lo W

    int tid = threadIdx.x;
    int bt = blockIdx.x >> 1, bs = blockIdx.x & 1;
    int w = tid >> 5, lane = tid & 31;
    int mg = w & 3, ng = w >> 2;
    int lr = lane >> 2, lc = lane & 3;

    uint32_t shh_u = (uint32_t)__cvta_generic_to_shared(shh);
    uint32_t shw_u = (uint32_t)__cvta_generic_to_shared(shw);
    int ar = lane & 15, ak = (lane >> 4) * 8;
    uint32_t aoff[2][2];
#pragma unroll
    for (int hl = 0; hl < 2; hl++)
#pragma unroll
        for (int ms = 0; ms < 2; ms++)
            aoff[hl][ms] = shh_u +
                (uint32_t)(((hl * 128 + (mg * 2 + ms) * 16 + ar) * SW + ak) * 2);
    int bsel = lane >> 4;
    int bw2 = lane & 15;
    int brow = bw2 & 7, bk = (bw2 >> 3) * 8;
    uint32_t boff[2];
#pragma unroll
    for (int hl = 0; hl < 2; hl++)
        boff[hl] = shw_u +
            (uint32_t)(((hl * 192 + (ng * 6 + bsel) * 8 + brow) * SW + bk) * 2);
    const uint32_t PRSTEP = 16 * SW * 2;

    float d[2][6][4];
#pragma unroll
    for (int ms = 0; ms < 2; ms++)
#pragma unroll
        for (int nt = 0; nt < 6; nt++)
#pragma unroll
            for (int j = 0; j < 4; j++) d[ms][nt][j] = 0.f;

    for (int kc = 0; kc < 8; kc++) {
#pragma unroll
        for (int i = tid; i < 2560; i += 512) {
            if (i < 1024) {
                int hl = i >> 9, r = (i & 511) >> 2, q = i & 3;
                const __nv_bfloat16* src = (hl ? g_hlo : g_hhi)
                    + ((size_t)(bt * 128 + r) << 8) + kc * 32;
                *(uint4*)(shh + (hl * 128 + r) * SW + q * 8) = ((const uint4*)src)[q];
            } else {
                int j = i - 1024;
                int hl = (j >= 768) ? 1 : 0, jj = j - hl * 768;
                int r = jj >> 2, q = jj & 3;
                const __nv_bfloat16* src = (hl ? g_w2lo : g_w2hi)
                    + ((size_t)(bs * 192 + r) << 8) + kc * 32;
                *(uint4*)(shw + (hl * 192 + r) * SW + q * 8) = ((const uint4*)src)[q];
            }
        }
        __syncthreads();

#pragma unroll
        for (int ks = 0; ks < 2; ks++) {
            uint32_t ka = ks * 32;
            uint32_t ah0[4], ah1[4], al0[4], al1[4];
            ldsm4(ah0, aoff[0][0] + ka);
            ldsm4(ah1, aoff[0][1] + ka);
            ldsm4(al0, aoff[1][0] + ka);
            ldsm4(al1, aoff[1][1] + ka);
#pragma unroll
            for (int pr = 0; pr < 3; pr++) {
                uint32_t bh[4], bl[4];
                ldsm4(bh, boff[0] + pr * PRSTEP + ka);
                ldsm4(bl, boff[1] + pr * PRSTEP + ka);
                int n0 = pr * 2, n1 = pr * 2 + 1;
                MMA_BF16(d[0][n0], ah0, bh[0], bh[1]);
                MMA_BF16(d[0][n0], ah0, bl[0], bl[1]);
                MMA_BF16(d[0][n0], al0, bh[0], bh[1]);
                MMA_BF16(d[1][n0], ah1, bh[0], bh[1]);
                MMA_BF16(d[1][n0], ah1, bl[0], bl[1]);
                MMA_BF16(d[1][n0], al1, bh[0], bh[1]);
                MMA_BF16(d[0][n1], ah0, bh[2], bh[3]);
                MMA_BF16(d[0][n1], ah0, bl[2], bl[3]);
                MMA_BF16(d[0][n1], al0, bh[2], bh[3]);
                MMA_BF16(d[1][n1], ah1, bh[2], bh[3]);
                MMA_BF16(d[1][n1], ah1, bl[2], bl[3]);
                MMA_BF16(d[1][n1], al1, bh[2], bh[3]);
            }
        }
        __syncthreads();
    }

#pragma unroll
    for (int ms = 0; ms < 2; ms++) {
#pragma unroll
        for (int nt = 0; nt < 6; nt++) {
            int node0 = bt * 128 + (mg * 2 + ms) * 16 + lr;
            int slot  = bs * 192 + (ng * 6 + nt) * 8 + lc * 2;
            if (node0 < NN)
                *(float2*)&g_prl[(size_t)node0 * PRLS + slot] =
                    make_float2(d[ms][nt][0], d[ms][nt][1]);
            if (node0 + 8 < NN)
                *(float2*)&g_prl[(size_t)(node0 + 8) * PRLS + slot] =
                    make_float2(d[ms][nt][2], d[ms][nt][3]);
        }
    }
}

// ---------------- launch 6: gather 2 + final epilogue + invariant restore ---------
__global__ __launch_bounds__(256) void gather2_final_kernel(
    const float* __restrict__ b2, const float* __restrict__ bl2,
    float* __restrict__ out)
{
    int t = blockIdx.x * blockDim.x + threadIdx.x;
    if (t == 0) g_base = 0;
    int n = t >> 5;
    if (n >= NN) return;
    int l = t & 31;
    int b = g_off[n], cnt = g_cnt[n], e2 = b + cnt;
    float invd = 1.f / fmaxf((float)cnt, 1.f);

    float4 a = make_float4(0.f, 0.f, 0.f, 0.f);
    int i = b;
    for (; i + 3 < e2; i += 4) {
        int s0 = g_adj[i], s1 = g_adj[i + 1], s2 = g_adj[i + 2], s3 = g_adj[i + 3];
        if (l < 31) {
            float4 v0 = *(const float4*)(g_prl + (size_t)s0 * PRLS + l * 4);
            float4 v1 = *(const float4*)(g_prl + (size_t)s1 * PRLS + l * 4);
            float4 v2 = *(const float4*)(g_prl + (size_t)s2 * PRLS + l * 4);
            float4 v3 = *(const float4*)(g_prl + (size_t)s3 * PRLS + l * 4);
            a.x += (v0.x + v1.x) + (v2.x + v3.x);
            a.y += (v0.y + v1.y) + (v2.y + v3.y);
            a.z += (v0.z + v1.z) + (v2.z + v3.z);
            a.w += (v0.w + v1.w) + (v2.w + v3.w);
        }
    }
    for (; i < e2; i++) {
        int s0 = g_adj[i];
        if (l < 31) {
            float4 v0 = *(const float4*)(g_prl + (size_t)s0 * PRLS + l * 4);
            a.x += v0.x; a.y += v0.y; a.z += v0.z; a.w += v0.w;
        }
    }
    if (l == 0) g_cnt[n] = 0;

    float4 tv = make_float4(0.f, 0.f, 0.f, 0.f);
    float4 l2v = make_float4(0.f, 0.f, 0.f, 0.f);
    int c = l * 4;
    if (l < 31) {
        float4 rr = *(const float4*)(g_prl + (size_t)n * PRLS + 128 + c);
        float4 ll = *(const float4*)(g_prl + (size_t)n * PRLS + 256 + c);
        float b0  = (c + 0 < NC) ? b2[c + 0] : 0.f;
        float bb1 = (c + 1 < NC) ? b2[c + 1] : 0.f;
        float bb2 = (c + 2 < NC) ? b2[c + 2] : 0.f;
        float b3  = (c + 3 < NC) ? b2[c + 3] : 0.f;
        tv.x = a.x * invd + b0  + rr.x;
        tv.y = a.y * invd + bb1 + rr.y;
        tv.z = a.z * invd + bb2 + rr.z;
        tv.w = a.w * invd + b3  + rr.w;
        l2v.x = ll.x + ((c + 0 < NC) ? bl2[c + 0] : 0.f);
        l2v.y = ll.y + ((c + 1 < NC) ? bl2[c + 1] : 0.f);
        l2v.z = ll.z + ((c + 2 < NC) ? bl2[c + 2] : 0.f);
        l2v.w = ll.w + ((c + 3 < NC) ? bl2[c + 3] : 0.f);
    }
    float s = tv.x*tv.x + tv.y*tv.y + tv.z*tv.z + tv.w*tv.w;
#pragma unroll
    for (int o = 16; o; o >>= 1) s += __shfl_xor_sync(0xffffffffu, s, o);
    float inv = 1.f / fmaxf(sqrtf(s), 1e-12f);

    float* orow = out + (size_t)n * NC;
    if (l < 30) {
        orow[c + 0] = tv.x * inv + l2v.x;
        orow[c + 1] = tv.y * inv + l2v.y;
        orow[c + 2] = tv.z * inv + l2v.z;
        orow[c + 3] = tv.w * inv + l2v.w;
    } else if (l == 30) {
        orow[120] = tv.x * inv + l2v.x;
    }
}

// ---------------- launcher ----------------------------------------------------------
extern "C" void kernel_launch(void* const* d_in, const int* in_sizes, int n_in,
                              void* d_out, int out_size)
{
    const float* x   = (const float*)d_in[0];
    const int*   ei  = (const int*)d_in[1];
    const float* w1l = (const float*)d_in[2];
    const float* b1  = (const float*)d_in[3];
    const float* w1r = (const float*)d_in[4];
    const float* wl1 = (const float*)d_in[5];
    const float* bl1 = (const float*)d_in[6];
    const float* w2l = (const float*)d_in[7];
    const float* b2  = (const float*)d_in[8];
    const float* w2r = (const float*)d_in[9];
    const float* wl2 = (const float*)d_in[10];
    const float* bl2 = (const float*)d_in[11];
    float* out = (float*)d_out;

    const int SMEM2 = (2 * 128 * SW + 2 * 192 * SW) * (int)sizeof(__nv_bfloat16); // 51200 B
    cudaFuncSetAttribute(gemm2_kernel,
                         cudaFuncAttributeMaxDynamicSharedMemorySize, SMEM2);

    histsetup_kernel   <<<(NE + 255) / 256, 256>>>(ei, w1l, w1r, wl1, w2l, w2r, wl2); // 1
    offsets_kernel     <<<(NN + 1023) / 1024, 1024>>>();                              // 2
    fill_kernel        <<<(NE + 255) / 256, 256>>>(ei);                               // 3
    gemm1_kernel       <<<NN / 16, 256>>>(x, b1, bl1);                                // 4 <- profiled
    gemm2_kernel       <<<(NNP / 128) * 2, 512, SMEM2>>>();                           // 5
    gather2_final_kernel<<<(NN * 32 + 255) / 256, 256>>>(b2, bl2, out);               // 6
}

// round 14
// speedup vs baseline: 1.0473x; 1.0473x over previous
#include <cuda_runtime.h>
#include <cuda_bf16.h>
#include <cstdint>
#include <math.h>

#define NN   50000
#define NNP  50048
#define NE   800000
#define IND  50
#define HID  256
#define NC   121
#define PRLS 384
#define SW   40
#define ASW  136
#define C1   512
#define K1M  128

typedef unsigned long long u64;

__device__ __align__(16) float g_prl [(size_t)NN * PRLS];
__device__ __align__(16) __nv_bfloat16 g_hhi[(size_t)NNP * HID];
__device__ __align__(16) __nv_bfloat16 g_hlo[(size_t)NNP * HID];
__device__ __align__(16) __nv_bfloat16 g_w1hi[C1 * K1M];
__device__ __align__(16) __nv_bfloat16 g_w1lo[C1 * K1M];
__device__ __align__(16) __nv_bfloat16 g_w2hi[PRLS * HID];
__device__ __align__(16) __nv_bfloat16 g_w2lo[PRLS * HID];
__device__ int g_cnt[NN];
__device__ int g_off[NN];
__device__ int g_cur[NN];
__device__ int g_adj[NE];
__device__ int g_base;

#define MMA_BF16(D, A, B0, B1)                                               \
    asm volatile("mma.sync.aligned.m16n8k16.row.col.f32.bf16.bf16.f32 "      \
                 "{%0,%1,%2,%3},{%4,%5,%6,%7},{%8,%9},{%0,%1,%2,%3};"        \
                 : "+f"(D[0]), "+f"(D[1]), "+f"(D[2]), "+f"(D[3])            \
                 : "r"(A[0]), "r"(A[1]), "r"(A[2]), "r"(A[3]),               \
                   "r"(B0), "r"(B1))

__device__ __forceinline__ void ldsm4(uint32_t* r, uint32_t addr) {
    asm volatile("ldmatrix.sync.aligned.m8n8.x4.shared.b16 {%0,%1,%2,%3}, [%4];"
                 : "=r"(r[0]), "=r"(r[1]), "=r"(r[2]), "=r"(r[3]) : "r"(addr));
}

__device__ __forceinline__ void split2(float a, float b, uint32_t& hiw, uint32_t& low) {
    __nv_bfloat16 ha = __float2bfloat16(a), hb = __float2bfloat16(b);
    __nv_bfloat16 la = __float2bfloat16(a - __bfloat162float(ha));
    __nv_bfloat16 lb = __float2bfloat16(b - __bfloat162float(hb));
    __nv_bfloat162 H, L;
    H.x = ha; H.y = hb; L.x = la; L.y = lb;
    hiw = *(uint32_t*)&H; low = *(uint32_t*)&L;
}

// ---------------- launch 1: histogram + weight packing ---------------------------
__global__ __launch_bounds__(256) void histsetup_kernel(
    const int* __restrict__ ei,
    const float* __restrict__ w1l, const float* __restrict__ w1r,
    const float* __restrict__ wl1,
    const float* __restrict__ w2l, const float* __restrict__ w2r,
    const float* __restrict__ wl2)
{
    int t = blockIdx.x * blockDim.x + threadIdx.x;
    if (t < NE) atomicAdd(&g_cnt[ei[NE + t]], 1);
    if (t < C1 * K1M) {
        int col = t >> 7, k = t & 127;
        float val = 0.f;
        if (col < HID) {
            if (k < IND)          val = w1l[k * HID + col];
            else if (k < 2 * IND) val = w1r[(k - IND) * HID + col];
        } else {
            if (k >= IND && k < 2 * IND) val = wl1[(k - IND) * HID + (col - HID)];
        }
        __nv_bfloat16 h = __float2bfloat16(val);
        g_w1hi[t] = h;
        g_w1lo[t] = __float2bfloat16(val - __bfloat162float(h));
    }
    if (t < PRLS * 32) {
        int slot = t >> 5, k0 = (t & 31) * 8;
        int seg = slot >> 7, idx = slot & 127;
        const float* w = (seg == 0) ? w2l : (seg == 1) ? w2r : wl2;
        union { __nv_bfloat16 b[8]; uint4 v; } H, L;
#pragma unroll
        for (int j = 0; j < 8; j++) {
            float val = (idx < NC) ? w[(k0 + j) * NC + idx] : 0.f;
            __nv_bfloat16 h = __float2bfloat16(val);
            H.b[j] = h;
            L.b[j] = __float2bfloat16(val - __bfloat162float(h));
        }
        *(uint4*)(g_w2hi + (size_t)slot * HID + k0) = H.v;
        *(uint4*)(g_w2lo + (size_t)slot * HID + k0) = L.v;
    }
}

// ---------------- launch 2: order-free CSR offsets -------------------------------
__global__ __launch_bounds__(1024) void offsets_kernel() {
    __shared__ int ws[32];
    __shared__ int sbase;
    int i = blockIdx.x * 1024 + threadIdx.x;
    int lane = threadIdx.x & 31, wid = threadIdx.x >> 5;
    int c = (i < NN) ? g_cnt[i] : 0;
    int v = c;
#pragma unroll
    for (int o = 1; o < 32; o <<= 1) {
        int u = __shfl_up_sync(0xffffffffu, v, o);
        if (lane >= o) v += u;
    }
    if (lane == 31) ws[wid] = v;
    __syncthreads();
    if (wid == 0) {
        int w = ws[lane];
#pragma unroll
        for (int o = 1; o < 32; o <<= 1) {
            int u = __shfl_up_sync(0xffffffffu, w, o);
            if (lane >= o) w += u;
        }
        ws[lane] = w;
    }
    __syncthreads();
    int excl = v - c + (wid ? ws[wid - 1] : 0);
    if (threadIdx.x == 1023) sbase = atomicAdd(&g_base, excl + c);
    __syncthreads();
    if (i < NN) { int o = sbase + excl; g_off[i] = o; g_cur[i] = o; }
}

// ---------------- launch 3: fill adjacency ---------------------------------------
__global__ __launch_bounds__(256) void fill_kernel(const int* __restrict__ ei) {
    int e = blockIdx.x * blockDim.x + threadIdx.x;
    if (e >= NE) return;
    int pos = atomicAdd(&g_cur[ei[NE + e]], 1);
    g_adj[pos] = ei[e];
}

// ---------------- launch 4 (PROFILED): fused gather + layer-1 MMA + norm + ELU ----
__global__ __launch_bounds__(512, 1) void gemm1_kernel(
    const float* __restrict__ x,
    const float* __restrict__ b1, const float* __restrict__ bl1)
{
    extern __shared__ __align__(16) char smem1[];
    __nv_bfloat16* sA = (__nv_bfloat16*)smem1;            // [2][64][ASW]
    __nv_bfloat16* sB = sA + 2 * 64 * ASW;                // [2][512][SW]
    float* spart = (float*)(sB + 2 * 512 * SW);           // [64][4]

    int tid = threadIdx.x;
    int w = tid >> 5, lane = tid & 31;
    int row0 = blockIdx.x * 64;

    // Phase A: each warp gathers 4 nodes
#pragma unroll 1
    for (int s = 0; s < 4; s++) {
        int r = w * 4 + s;
        int n = row0 + r;
        bool valid = n < NN;
        int b = valid ? g_off[n] : 0, cnt = valid ? g_cnt[n] : 0, e2 = b + cnt;
        float inv = 1.f / fmaxf((float)cnt, 1.f);
        bool act = lane < 25;
        float2 a = make_float2(0.f, 0.f);
        int i = b;
        for (; i + 3 < e2; i += 4) {
            int s0 = g_adj[i], s1 = g_adj[i + 1], s2 = g_adj[i + 2], s3 = g_adj[i + 3];
            if (act) {
                float2 v0 = *((const float2*)(x + (size_t)s0 * IND) + lane);
                float2 v1 = *((const float2*)(x + (size_t)s1 * IND) + lane);
                float2 v2 = *((const float2*)(x + (size_t)s2 * IND) + lane);
                float2 v3 = *((const float2*)(x + (size_t)s3 * IND) + lane);
                a.x += (v0.x + v1.x) + (v2.x + v3.x);
                a.y += (v0.y + v1.y) + (v2.y + v3.y);
            }
        }
        for (; i < e2; i++) {
            int s0 = g_adj[i];
            if (act) {
                float2 v0 = *((const float2*)(x + (size_t)s0 * IND) + lane);
                a.x += v0.x; a.y += v0.y;
            }
        }
        if (act) {
            uint32_t hm, lm;
            split2(a.x * inv, a.y * inv, hm, lm);
            *(uint32_t*)(sA + (0 * 64 + r) * ASW + 2 * lane) = hm;
            *(uint32_t*)(sA + (1 * 64 + r) * ASW + 2 * lane) = lm;
            float2 xv = valid ? *((const float2*)(x + (size_t)n * IND) + lane)
                              : make_float2(0.f, 0.f);
            uint32_t hx, lx;
            split2(xv.x, xv.y, hx, lx);
            *(uint32_t*)(sA + (0 * 64 + r) * ASW + 50 + 2 * lane) = hx;
            *(uint32_t*)(sA + (1 * 64 + r) * ASW + 50 + 2 * lane) = lx;
        } else {
            int c0 = 100 + (lane - 25) * 4;
            *(uint2*)(sA + (0 * 64 + r) * ASW + c0) = make_uint2(0u, 0u);
            *(uint2*)(sA + (1 * 64 + r) * ASW + c0) = make_uint2(0u, 0u);
        }
    }
    __syncthreads();

    // Phase B: MMA
    int mg = w >> 2, ng = w & 3;
    int lr = lane >> 2, lc = lane & 3;

    uint32_t sA_u = (uint32_t)__cvta_generic_to_shared(sA);
    uint32_t sB_u = (uint32_t)__cvta_generic_to_shared(sB);
    int ar = lane & 15, ak = (lane >> 4) * 8;
    uint32_t aoff[2];
#pragma unroll
    for (int hl = 0; hl < 2; hl++)
        aoff[hl] = sA_u + (uint32_t)(((hl * 64 + mg * 16 + ar) * ASW + ak) * 2);
    int bsel = lane >> 4, bw2 = lane & 15;
    int brow = bw2 & 7, bk = (bw2 >> 3) * 8;
    uint32_t boff[2][2];
#pragma unroll
    for (int hl = 0; hl < 2; hl++)
#pragma unroll
        for (int h = 0; h < 2; h++)
            boff[hl][h] = sB_u +
                (uint32_t)(((hl * 512 + h * 256 + ng * 64 + bsel * 8 + brow) * SW + bk) * 2);
    const uint32_t PRSTEP = 16 * SW * 2;

    float d[2][8][4];
#pragma unroll
    for (int h = 0; h < 2; h++)
#pragma unroll
        for (int nt = 0; nt < 8; nt++)
#pragma unroll
            for (int j = 0; j < 4; j++) d[h][nt][j] = 0.f;

    for (int kc = 0; kc < 4; kc++) {
#pragma unroll
        for (int i = tid; i < 4096; i += 512) {
            int hl = i >> 11, rem = i & 2047;
            int col = rem >> 2, q = rem & 3;
            const __nv_bfloat16* src = (hl ? g_w1lo : g_w1hi)
                + (size_t)col * K1M + kc * 32 + q * 8;
            *(uint4*)(sB + (hl * 512 + col) * SW + q * 8) = *(const uint4*)src;
        }
        __syncthreads();

#pragma unroll
        for (int ks = 0; ks < 2; ks++) {
            uint32_t ka = (uint32_t)((kc * 32 + ks * 16) * 2);
            uint32_t kb = (uint32_t)(ks * 32);
            uint32_t ah[4], al[4];
            ldsm4(ah, aoff[0] + ka);
            ldsm4(al, aoff[1] + ka);
#pragma unroll
            for (int h = 0; h < 2; h++) {
#pragma unroll
                for (int pr = 0; pr < 4; pr++) {
                    uint32_t bh[4], bl[4];
                    ldsm4(bh, boff[0][h] + pr * PRSTEP + kb);
                    ldsm4(bl, boff[1][h] + pr * PRSTEP + kb);
                    int n0 = pr * 2, n1 = pr * 2 + 1;
                    MMA_BF16(d[h][n0], ah, bh[0], bh[1]);
                    MMA_BF16(d[h][n0], ah, bl[0], bl[1]);
                    MMA_BF16(d[h][n0], al, bh[0], bh[1]);
                    MMA_BF16(d[h][n1], ah, bh[2], bh[3]);
                    MMA_BF16(d[h][n1], ah, bl[2], bl[3]);
                    MMA_BF16(d[h][n1], al, bh[2], bh[3]);
                }
            }
        }
        __syncthreads();
    }

    // Epilogue: add biases, L2 norm over acc cols, z = acc*inv + lin, ELU, bf16 out
#pragma unroll
    for (int nt = 0; nt < 8; nt++) {
        int col = ng * 64 + nt * 8 + lc * 2;
        float bb0 = b1[col], bb1v = b1[col + 1];
        float lb0 = bl1[col], lb1 = bl1[col + 1];
        d[0][nt][0] += bb0;  d[0][nt][1] += bb1v;
        d[0][nt][2] += bb0;  d[0][nt][3] += bb1v;
        d[1][nt][0] += lb0;  d[1][nt][1] += lb1;
        d[1][nt][2] += lb0;  d[1][nt][3] += lb1;
    }
    float ss0 = 0.f, ss1 = 0.f;
#pragma unroll
    for (int nt = 0; nt < 8; nt++) {
        ss0 += d[0][nt][0] * d[0][nt][0] + d[0][nt][1] * d[0][nt][1];
        ss1 += d[0][nt][2] * d[0][nt][2] + d[0][nt][3] * d[0][nt][3];
    }
    ss0 += __shfl_xor_sync(0xffffffffu, ss0, 1);
    ss0 += __shfl_xor_sync(0xffffffffu, ss0, 2);
    ss1 += __shfl_xor_sync(0xffffffffu, ss1, 1);
    ss1 += __shfl_xor_sync(0xffffffffu, ss1, 2);
    if (lc == 0) {
        spart[(mg * 16 + lr) * 4 + ng] = ss0;
        spart[(mg * 16 + lr + 8) * 4 + ng] = ss1;
    }
    __syncthreads();
    float s0 = spart[(mg * 16 + lr) * 4 + 0] + spart[(mg * 16 + lr) * 4 + 1]
             + spart[(mg * 16 + lr) * 4 + 2] + spart[(mg * 16 + lr) * 4 + 3];
    float s1 = spart[(mg * 16 + lr + 8) * 4 + 0] + spart[(mg * 16 + lr + 8) * 4 + 1]
             + spart[(mg * 16 + lr + 8) * 4 + 2] + spart[(mg * 16 + lr + 8) * 4 + 3];
    float inv0 = 1.f / fmaxf(sqrtf(s0), 1e-12f);
    float inv1 = 1.f / fmaxf(sqrtf(s1), 1e-12f);

    int node0 = row0 + mg * 16 + lr;
#pragma unroll
    for (int nt = 0; nt < 8; nt++) {
        int col = ng * 64 + nt * 8 + lc * 2;
        float z0 = d[0][nt][0] * inv0 + d[1][nt][0];
        float z1 = d[0][nt][1] * inv0 + d[1][nt][1];
        float z2 = d[0][nt][2] * inv1 + d[1][nt][2];
        float z3 = d[0][nt][3] * inv1 + d[1][nt][3];
        z0 = (z0 > 0.f) ? z0 : expm1f(z0);
        z1 = (z1 > 0.f) ? z1 : expm1f(z1);
        z2 = (z2 > 0.f) ? z2 : expm1f(z2);
        z3 = (z3 > 0.f) ? z3 : expm1f(z3);
        uint32_t hw, lw;
        split2(z0, z1, hw, lw);
        *(uint32_t*)(g_hhi + (size_t)node0 * HID + col) = hw;
        *(uint32_t*)(g_hlo + (size_t)node0 * HID + col) = lw;
        split2(z2, z3, hw, lw);
        *(uint32_t*)(g_hhi + (size_t)(node0 + 8) * HID + col) = hw;
        *(uint32_t*)(g_hlo + (size_t)(node0 + 8) * HID + col) = lw;
    }
}

// ---------------- launch 5: layer-2 GEMM via mma.sync bf16x3 + ldmatrix -----------
__global__ __launch_bounds__(512, 1) void gemm2_kernel()
{
    extern __shared__ __align__(16) __nv_bfloat16 smem[];
    __nv_bfloat16* shh = smem;
    __nv_bfloat16* shw = smem + 2 * 128 * SW;

    int tid = threadIdx.x;
    int bt = blockIdx.x >> 1, bs = blockIdx.x & 1;
    int w = tid >> 5, lane = tid & 31;
    int mg = w & 3, ng = w >> 2;
    int lr = lane >> 2, lc = lane & 3;

    uint32_t shh_u = (uint32_t)__cvta_generic_to_shared(shh);
    uint32_t shw_u = (uint32_t)__cvta_generic_to_shared(shw);
    int ar = lane & 15, ak = (lane >> 4) * 8;
    uint32_t aoff[2][2];
#pragma unroll
    for (int hl = 0; hl < 2; hl++)
#pragma unroll
        for (int ms = 0; ms < 2; ms++)
            aoff[hl][ms] = shh_u +
                (uint32_t)(((hl * 128 + (mg * 2 + ms) * 16 + ar) * SW + ak) * 2);
    int bsel = lane >> 4, bw2 = lane & 15;
    int brow = bw2 & 7, bk = (bw2 >> 3) * 8;
    uint32_t boff[2];
#pragma unroll
    for (int hl = 0; hl < 2; hl++)
        boff[hl] = shw_u +
            (uint32_t)(((hl * 192 + (ng * 6 + bsel) * 8 + brow) * SW + bk) * 2);
    const uint32_t PRSTEP = 16 * SW * 2;

    float d[2][6][4];
#pragma unroll
    for (int ms = 0; ms < 2; ms++)
#pragma unroll
        for (int nt = 0; nt < 6; nt++)
#pragma unroll
            for (int j = 0; j < 4; j++) d[ms][nt][j] = 0.f;

    for (int kc = 0; kc < 8; kc++) {
#pragma unroll
        for (int i = tid; i < 2560; i += 512) {
            if (i < 1024) {
                int hl = i >> 9, r = (i & 511) >> 2, q = i & 3;
                const __nv_bfloat16* src = (hl ? g_hlo : g_hhi)
                    + ((size_t)(bt * 128 + r) << 8) + kc * 32;
                *(uint4*)(shh + (hl * 128 + r) * SW + q * 8) = ((const uint4*)src)[q];
            } else {
                int j = i - 1024;
                int hl = (j >= 768) ? 1 : 0, jj = j - hl * 768;
                int r = jj >> 2, q = jj & 3;
                const __nv_bfloat16* src = (hl ? g_w2lo : g_w2hi)
                    + ((size_t)(bs * 192 + r) << 8) + kc * 32;
                *(uint4*)(shw + (hl * 192 + r) * SW + q * 8) = ((const uint4*)src)[q];
            }
        }
        __syncthreads();

#pragma unroll
        for (int ks = 0; ks < 2; ks++) {
            uint32_t ka = ks * 32;
            uint32_t ah0[4], ah1[4], al0[4], al1[4];
            ldsm4(ah0, aoff[0][0] + ka);
            ldsm4(ah1, aoff[0][1] + ka);
            ldsm4(al0, aoff[1][0] + ka);
            ldsm4(al1, aoff[1][1] + ka);
#pragma unroll
            for (int pr = 0; pr < 3; pr++) {
                uint32_t bh[4], bl[4];
                ldsm4(bh, boff[0] + pr * PRSTEP + ka);
                ldsm4(bl, boff[1] + pr * PRSTEP + ka);
                int n0 = pr * 2, n1 = pr * 2 + 1;
                MMA_BF16(d[0][n0], ah0, bh[0], bh[1]);
                MMA_BF16(d[0][n0], ah0, bl[0], bl[1]);
                MMA_BF16(d[0][n0], al0, bh[0], bh[1]);
                MMA_BF16(d[1][n0], ah1, bh[0], bh[1]);
                MMA_BF16(d[1][n0], ah1, bl[0], bl[1]);
                MMA_BF16(d[1][n0], al1, bh[0], bh[1]);
                MMA_BF16(d[0][n1], ah0, bh[2], bh[3]);
                MMA_BF16(d[0][n1], ah0, bl[2], bl[3]);
                MMA_BF16(d[0][n1], al0, bh[2], bh[3]);
                MMA_BF16(d[1][n1], ah1, bh[2], bh[3]);
                MMA_BF16(d[1][n1], ah1, bl[2], bl[3]);
                MMA_BF16(d[1][n1], al1, bh[2], bh[3]);
            }
        }
        __syncthreads();
    }

#pragma unroll
    for (int ms = 0; ms < 2; ms++) {
#pragma unroll
        for (int nt = 0; nt < 6; nt++) {
            int node0 = bt * 128 + (mg * 2 + ms) * 16 + lr;
            int slot  = bs * 192 + (ng * 6 + nt) * 8 + lc * 2;
            if (node0 < NN)
                *(float2*)&g_prl[(size_t)node0 * PRLS + slot] =
                    make_float2(d[ms][nt][0], d[ms][nt][1]);
            if (node0 + 8 < NN)
                *(float2*)&g_prl[(size_t)(node0 + 8) * PRLS + slot] =
                    make_float2(d[ms][nt][2], d[ms][nt][3]);
        }
    }
}

// ---------------- launch 6: gather 2 + final epilogue + invariant restore ---------
__global__ __launch_bounds__(256) void gather2_final_kernel(
    const float* __restrict__ b2, const float* __restrict__ bl2,
    float* __restrict__ out)
{
    int t = blockIdx.x * blockDim.x + threadIdx.x;
    if (t == 0) g_base = 0;
    int n = t >> 5;
    if (n >= NN) return;
    int l = t & 31;
    int b = g_off[n], cnt = g_cnt[n], e2 = b + cnt;
    float invd = 1.f / fmaxf((float)cnt, 1.f);

    float4 a = make_float4(0.f, 0.f, 0.f, 0.f);
    int i = b;
    for (; i + 3 < e2; i += 4) {
        int s0 = g_adj[i], s1 = g_adj[i + 1], s2 = g_adj[i + 2], s3 = g_adj[i + 3];
        if (l < 31) {
            float4 v0 = *(const float4*)(g_prl + (size_t)s0 * PRLS + l * 4);
            float4 v1 = *(const float4*)(g_prl + (size_t)s1 * PRLS + l * 4);
            float4 v2 = *(const float4*)(g_prl + (size_t)s2 * PRLS + l * 4);
            float4 v3 = *(const float4*)(g_prl + (size_t)s3 * PRLS + l * 4);
            a.x += (v0.x + v1.x) + (v2.x + v3.x);
            a.y += (v0.y + v1.y) + (v2.y + v3.y);
            a.z += (v0.z + v1.z) + (v2.z + v3.z);
            a.w += (v0.w + v1.w) + (v2.w + v3.w);
        }
    }
    for (; i < e2; i++) {
        int s0 = g_adj[i];
        if (l < 31) {
            float4 v0 = *(const float4*)(g_prl + (size_t)s0 * PRLS + l * 4);
            a.x += v0.x; a.y += v0.y; a.z += v0.z; a.w += v0.w;
        }
    }
    if (l == 0) g_cnt[n] = 0;

    float4 tv = make_float4(0.f, 0.f, 0.f, 0.f);
    float4 l2v = make_float4(0.f, 0.f, 0.f, 0.f);
    int c = l * 4;
    if (l < 31) {
        float4 rr = *(const float4*)(g_prl + (size_t)n * PRLS + 128 + c);
        float4 ll = *(const float4*)(g_prl + (size_t)n * PRLS + 256 + c);
        float b0  = (c + 0 < NC) ? b2[c + 0] : 0.f;
        float bb1 = (c + 1 < NC) ? b2[c + 1] : 0.f;
        float bb2 = (c + 2 < NC) ? b2[c + 2] : 0.f;
        float b3  = (c + 3 < NC) ? b2[c + 3] : 0.f;
        tv.x = a.x * invd + b0  + rr.x;
        tv.y = a.y * invd + bb1 + rr.y;
        tv.z = a.z * invd + bb2 + rr.z;
        tv.w = a.w * invd + b3  + rr.w;
        l2v.x = ll.x + ((c + 0 < NC) ? bl2[c + 0] : 0.f);
        l2v.y = ll.y + ((c + 1 < NC) ? bl2[c + 1] : 0.f);
        l2v.z = ll.z + ((c + 2 < NC) ? bl2[c + 2] : 0.f);
        l2v.w = ll.w + ((c + 3 < NC) ? bl2[c + 3] : 0.f);
    }
    float s = tv.x*tv.x + tv.y*tv.y + tv.z*tv.z + tv.w*tv.w;
#pragma unroll
    for (int o = 16; o; o >>= 1) s += __shfl_xor_sync(0xffffffffu, s, o);
    float inv = 1.f / fmaxf(sqrtf(s), 1e-12f);

    float* orow = out + (size_t)n * NC;
    if (l < 30) {
        orow[c + 0] = tv.x * inv + l2v.x;
        orow[c + 1] = tv.y * inv + l2v.y;
        orow[c + 2] = tv.z * inv + l2v.z;
        orow[c + 3] = tv.w * inv + l2v.w;
    } else if (l == 30) {
        orow[120] = tv.x * inv + l2v.x;
    }
}

// ---------------- launcher ----------------------------------------------------------
extern "C" void kernel_launch(void* const* d_in, const int* in_sizes, int n_in,
                              void* d_out, int out_size)
{
    const float* x   = (const float*)d_in[0];
    const int*   ei  = (const int*)d_in[1];
    const float* w1l = (const float*)d_in[2];
    const float* b1  = (const float*)d_in[3];
    const float* w1r = (const float*)d_in[4];
    const float* wl1 = (const float*)d_in[5];
    const float* bl1 = (const float*)d_in[6];
    const float* w2l = (const float*)d_in[7];
    const float* b2  = (const float*)d_in[8];
    const float* w2r = (const float*)d_in[9];
    const float* wl2 = (const float*)d_in[10];
    const float* bl2 = (const float*)d_in[11];
    float* out = (float*)d_out;

    const int SMEM2 = (2 * 128 * SW + 2 * 192 * SW) * (int)sizeof(__nv_bfloat16);
    const int SMEM1 = (2 * 64 * ASW + 2 * 512 * SW) * (int)sizeof(__nv_bfloat16)
                    + 64 * 4 * (int)sizeof(float);
    cudaFuncSetAttribute(gemm2_kernel,
                         cudaFuncAttributeMaxDynamicSharedMemorySize, SMEM2);
    cudaFuncSetAttribute(gemm1_kernel,
                         cudaFuncAttributeMaxDynamicSharedMemorySize, SMEM1);

    histsetup_kernel   <<<(NE + 255) / 256, 256>>>(ei, w1l, w1r, wl1, w2l, w2r, wl2); // 1
    offsets_kernel     <<<(NN + 1023) / 1024, 1024>>>();                              // 2
    fill_kernel        <<<(NE + 255) / 256, 256>>>(ei);                               // 3
    gemm1_kernel       <<<NNP / 64, 512, SMEM1>>>(x, b1, bl1);                        // 4 <- profiled
    gemm2_kernel       <<<(NNP / 128) * 2, 512, SMEM2>>>();                           // 5
    gather2_final_kernel<<<(NN * 32 + 255) / 256, 256>>>(b2, bl2, out);               // 6
}

// round 15
// speedup vs baseline: 1.0986x; 1.0490x over previous
#include <cuda_runtime.h>
#include <cuda_bf16.h>
#include <cstdint>
#include <math.h>

#define NN   50000
#define NNP  50048
#define NE   800000
#define IND  50
#define HID  256
#define NC   121
#define PRLS 384
#define SW   40
#define ASW  136
#define C1   512
#define K1M  128

typedef unsigned long long u64;

// INVARIANT: g_cnt[] == 0 and g_base == 0 at kernel_launch entry (BSS + restore).
__device__ __align__(16) float g_prl [(size_t)NN * PRLS];
__device__ __align__(16) __nv_bfloat16 g_ahi[(size_t)NNP * K1M];  // A rows: mean|x|0 hi
__device__ __align__(16) __nv_bfloat16 g_alo[(size_t)NNP * K1M];  // A rows lo
__device__ __align__(16) __nv_bfloat16 g_hhi[(size_t)NNP * HID];
__device__ __align__(16) __nv_bfloat16 g_hlo[(size_t)NNP * HID];
__device__ __align__(16) __nv_bfloat16 g_w1hi[C1 * K1M];
__device__ __align__(16) __nv_bfloat16 g_w1lo[C1 * K1M];
__device__ __align__(16) __nv_bfloat16 g_w2hi[PRLS * HID];
__device__ __align__(16) __nv_bfloat16 g_w2lo[PRLS * HID];
__device__ int g_cnt[NN];
__device__ int g_off[NN];
__device__ int g_cur[NN];
__device__ int g_adj[NE];
__device__ int g_base;

#define MMA_BF16(D, A, B0, B1)                                               \
    asm volatile("mma.sync.aligned.m16n8k16.row.col.f32.bf16.bf16.f32 "      \
                 "{%0,%1,%2,%3},{%4,%5,%6,%7},{%8,%9},{%0,%1,%2,%3};"        \
                 : "+f"(D[0]), "+f"(D[1]), "+f"(D[2]), "+f"(D[3])            \
                 : "r"(A[0]), "r"(A[1]), "r"(A[2]), "r"(A[3]),               \
                   "r"(B0), "r"(B1))

__device__ __forceinline__ void ldsm4(uint32_t* r, uint32_t addr) {
    asm volatile("ldmatrix.sync.aligned.m8n8.x4.shared.b16 {%0,%1,%2,%3}, [%4];"
                 : "=r"(r[0]), "=r"(r[1]), "=r"(r[2]), "=r"(r[3]) : "r"(addr));
}

__device__ __forceinline__ void split2(float a, float b, uint32_t& hiw, uint32_t& low) {
    __nv_bfloat16 ha = __float2bfloat16(a), hb = __float2bfloat16(b);
    __nv_bfloat16 la = __float2bfloat16(a - __bfloat162float(ha));
    __nv_bfloat16 lb = __float2bfloat16(b - __bfloat162float(hb));
    __nv_bfloat162 H, L;
    H.x = ha; H.y = hb; L.x = la; L.y = lb;
    hiw = *(uint32_t*)&H; low = *(uint32_t*)&L;
}

// ---------------- launch 1: histogram + weight packing ---------------------------
__global__ __launch_bounds__(256) void histsetup_kernel(
    const int* __restrict__ ei,
    const float* __restrict__ w1l, const float* __restrict__ w1r,
    const float* __restrict__ wl1,
    const float* __restrict__ w2l, const float* __restrict__ w2r,
    const float* __restrict__ wl2)
{
    int t = blockIdx.x * blockDim.x + threadIdx.x;
    if (t < NE) atomicAdd(&g_cnt[ei[NE + t]], 1);
    if (t < C1 * K1M) {
        int col = t >> 7, k = t & 127;
        float val = 0.f;
        if (col < HID) {
            if (k < IND)          val = w1l[k * HID + col];
            else if (k < 2 * IND) val = w1r[(k - IND) * HID + col];
        } else {
            if (k >= IND && k < 2 * IND) val = wl1[(k - IND) * HID + (col - HID)];
        }
        __nv_bfloat16 h = __float2bfloat16(val);
        g_w1hi[t] = h;
        g_w1lo[t] = __float2bfloat16(val - __bfloat162float(h));
    }
    if (t < PRLS * 32) {
        int slot = t >> 5, k0 = (t & 31) * 8;
        int seg = slot >> 7, idx = slot & 127;
        const float* w = (seg == 0) ? w2l : (seg == 1) ? w2r : wl2;
        union { __nv_bfloat16 b[8]; uint4 v; } H, L;
#pragma unroll
        for (int j = 0; j < 8; j++) {
            float val = (idx < NC) ? w[(k0 + j) * NC + idx] : 0.f;
            __nv_bfloat16 h = __float2bfloat16(val);
            H.b[j] = h;
            L.b[j] = __float2bfloat16(val - __bfloat162float(h));
        }
        *(uint4*)(g_w2hi + (size_t)slot * HID + k0) = H.v;
        *(uint4*)(g_w2lo + (size_t)slot * HID + k0) = L.v;
    }
}

// ---------------- launch 2: order-free CSR offsets -------------------------------
__global__ __launch_bounds__(1024) void offsets_kernel() {
    __shared__ int ws[32];
    __shared__ int sbase;
    int i = blockIdx.x * 1024 + threadIdx.x;
    int lane = threadIdx.x & 31, wid = threadIdx.x >> 5;
    int c = (i < NN) ? g_cnt[i] : 0;
    int v = c;
#pragma unroll
    for (int o = 1; o < 32; o <<= 1) {
        int u = __shfl_up_sync(0xffffffffu, v, o);
        if (lane >= o) v += u;
    }
    if (lane == 31) ws[wid] = v;
    __syncthreads();
    if (wid == 0) {
        int w = ws[lane];
#pragma unroll
        for (int o = 1; o < 32; o <<= 1) {
            int u = __shfl_up_sync(0xffffffffu, w, o);
            if (lane >= o) w += u;
        }
        ws[lane] = w;
    }
    __syncthreads();
    int excl = v - c + (wid ? ws[wid - 1] : 0);
    if (threadIdx.x == 1023) sbase = atomicAdd(&g_base, excl + c);
    __syncthreads();
    if (i < NN) { int o = sbase + excl; g_off[i] = o; g_cur[i] = o; }
}

// ---------------- launch 3: fill adjacency ---------------------------------------
__global__ __launch_bounds__(256) void fill_kernel(const int* __restrict__ ei) {
    int e = blockIdx.x * blockDim.x + threadIdx.x;
    if (e >= NE) return;
    int pos = atomicAdd(&g_cur[ei[NE + e]], 1);
    g_adj[pos] = ei[e];
}

// ---------------- launch 4 (profiled): gather 1 -> bf16 hi/lo A rows --------------
// warp per node; lanes 0..24 mean+x cols, lanes 25..31 zero pads. Covers NNP rows.
__global__ __launch_bounds__(256) void gather1_kernel(const float* __restrict__ x) {
    int t = blockIdx.x * blockDim.x + threadIdx.x;
    int n = t >> 5;
    if (n >= NNP) return;
    int l = t & 31;
    bool valid = n < NN;
    int b = valid ? g_off[n] : 0, cnt = valid ? g_cnt[n] : 0, e2 = b + cnt;
    float inv = 1.f / fmaxf((float)cnt, 1.f);
    bool act = l < 25;
    float2 a = make_float2(0.f, 0.f);
    int i = b;
    for (; i + 3 < e2; i += 4) {
        int s0 = g_adj[i], s1 = g_adj[i + 1], s2 = g_adj[i + 2], s3 = g_adj[i + 3];
        if (act) {
            float2 v0 = *((const float2*)(x + (size_t)s0 * IND) + l);
            float2 v1 = *((const float2*)(x + (size_t)s1 * IND) + l);
            float2 v2 = *((const float2*)(x + (size_t)s2 * IND) + l);
            float2 v3 = *((const float2*)(x + (size_t)s3 * IND) + l);
            a.x += (v0.x + v1.x) + (v2.x + v3.x);
            a.y += (v0.y + v1.y) + (v2.y + v3.y);
        }
    }
    for (; i < e2; i++) {
        int s0 = g_adj[i];
        if (act) {
            float2 v0 = *((const float2*)(x + (size_t)s0 * IND) + l);
            a.x += v0.x; a.y += v0.y;
        }
    }
    __nv_bfloat16* ahi = g_ahi + (size_t)n * K1M;
    __nv_bfloat16* alo = g_alo + (size_t)n * K1M;
    if (act) {
        uint32_t hw, lw;
        split2(a.x * inv, a.y * inv, hw, lw);
        *(uint32_t*)(ahi + 2 * l) = hw;
        *(uint32_t*)(alo + 2 * l) = lw;
        float2 xv = valid ? *((const float2*)(x + (size_t)n * IND) + l)
                          : make_float2(0.f, 0.f);
        split2(xv.x, xv.y, hw, lw);
        *(uint32_t*)(ahi + 50 + 2 * l) = hw;
        *(uint32_t*)(alo + 50 + 2 * l) = lw;
    } else {
        int c0 = 100 + (l - 25) * 4;
        *(uint2*)(ahi + c0) = make_uint2(0u, 0u);
        *(uint2*)(alo + c0) = make_uint2(0u, 0u);
    }
}

// ---------------- launch 5: layer-1 MMA GEMM + bias + norm + ELU ------------------
// block: 64 nodes x 512 cols (acc 256 | lin 256), 512 threads, pure MMA.
__global__ __launch_bounds__(512, 1) void gemm1_kernel(
    const float* __restrict__ b1, const float* __restrict__ bl1)
{
    extern __shared__ __align__(16) char smem1[];
    __nv_bfloat16* sA = (__nv_bfloat16*)smem1;            // [2][64][ASW]
    __nv_bfloat16* sB = sA + 2 * 64 * ASW;                // [2][512][SW]
    float* spart = (float*)(sB + 2 * 512 * SW);           // [64][4]

    int tid = threadIdx.x;
    int w = tid >> 5, lane = tid & 31;
    int row0 = blockIdx.x * 64;

    // A tile copy: verbatim rows from g_ahi/g_alo
#pragma unroll
    for (int i = tid; i < 2048; i += 512) {
        int hl = i >> 10, rem = i & 1023;
        int r = rem >> 4, q = rem & 15;
        const __nv_bfloat16* src = (hl ? g_alo : g_ahi)
            + (size_t)(row0 + r) * K1M + q * 8;
        *(uint4*)(sA + (hl * 64 + r) * ASW + q * 8) = *(const uint4*)src;
    }

    int mg = w >> 2, ng = w & 3;
    int lr = lane >> 2, lc = lane & 3;

    uint32_t sA_u = (uint32_t)__cvta_generic_to_shared(sA);
    uint32_t sB_u = (uint32_t)__cvta_generic_to_shared(sB);
    int ar = lane & 15, ak = (lane >> 4) * 8;
    uint32_t aoff[2];
#pragma unroll
    for (int hl = 0; hl < 2; hl++)
        aoff[hl] = sA_u + (uint32_t)(((hl * 64 + mg * 16 + ar) * ASW + ak) * 2);
    int bsel = lane >> 4, bw2 = lane & 15;
    int brow = bw2 & 7, bk = (bw2 >> 3) * 8;
    uint32_t boff[2][2];
#pragma unroll
    for (int hl = 0; hl < 2; hl++)
#pragma unroll
        for (int h = 0; h < 2; h++)
            boff[hl][h] = sB_u +
                (uint32_t)(((hl * 512 + h * 256 + ng * 64 + bsel * 8 + brow) * SW + bk) * 2);
    const uint32_t PRSTEP = 16 * SW * 2;

    float d[2][8][4];
#pragma unroll
    for (int h = 0; h < 2; h++)
#pragma unroll
        for (int nt = 0; nt < 8; nt++)
#pragma unroll
            for (int j = 0; j < 4; j++) d[h][nt][j] = 0.f;

    for (int kc = 0; kc < 4; kc++) {
#pragma unroll
        for (int i = tid; i < 4096; i += 512) {
            int hl = i >> 11, rem = i & 2047;
            int col = rem >> 2, q = rem & 3;
            const __nv_bfloat16* src = (hl ? g_w1lo : g_w1hi)
                + (size_t)col * K1M + kc * 32 + q * 8;
            *(uint4*)(sB + (hl * 512 + col) * SW + q * 8) = *(const uint4*)src;
        }
        __syncthreads();

#pragma unroll
        for (int ks = 0; ks < 2; ks++) {
            uint32_t ka = (uint32_t)((kc * 32 + ks * 16) * 2);
            uint32_t kb = (uint32_t)(ks * 32);
            uint32_t ah[4], al[4];
            ldsm4(ah, aoff[0] + ka);
            ldsm4(al, aoff[1] + ka);
#pragma unroll
            for (int h = 0; h < 2; h++) {
#pragma unroll
                for (int pr = 0; pr < 4; pr++) {
                    uint32_t bh[4], bl[4];
                    ldsm4(bh, boff[0][h] + pr * PRSTEP + kb);
                    ldsm4(bl, boff[1][h] + pr * PRSTEP + kb);
                    int n0 = pr * 2, n1 = pr * 2 + 1;
                    MMA_BF16(d[h][n0], ah, bh[0], bh[1]);
                    MMA_BF16(d[h][n0], ah, bl[0], bl[1]);
                    MMA_BF16(d[h][n0], al, bh[0], bh[1]);
                    MMA_BF16(d[h][n1], ah, bh[2], bh[3]);
                    MMA_BF16(d[h][n1], ah, bl[2], bl[3]);
                    MMA_BF16(d[h][n1], al, bh[2], bh[3]);
                }
            }
        }
        __syncthreads();
    }

    // Epilogue
#pragma unroll
    for (int nt = 0; nt < 8; nt++) {
        int col = ng * 64 + nt * 8 + lc * 2;
        float bb0 = b1[col], bb1v = b1[col + 1];
        float lb0 = bl1[col], lb1 = bl1[col + 1];
        d[0][nt][0] += bb0;  d[0][nt][1] += bb1v;
        d[0][nt][2] += bb0;  d[0][nt][3] += bb1v;
        d[1][nt][0] += lb0;  d[1][nt][1] += lb1;
        d[1][nt][2] += lb0;  d[1][nt][3] += lb1;
    }
    float ss0 = 0.f, ss1 = 0.f;
#pragma unroll
    for (int nt = 0; nt < 8; nt++) {
        ss0 += d[0][nt][0] * d[0][nt][0] + d[0][nt][1] * d[0][nt][1];
        ss1 += d[0][nt][2] * d[0][nt][2] + d[0][nt][3] * d[0][nt][3];
    }
    ss0 += __shfl_xor_sync(0xffffffffu, ss0, 1);
    ss0 += __shfl_xor_sync(0xffffffffu, ss0, 2);
    ss1 += __shfl_xor_sync(0xffffffffu, ss1, 1);
    ss1 += __shfl_xor_sync(0xffffffffu, ss1, 2);
    if (lc == 0) {
        spart[(mg * 16 + lr) * 4 + ng] = ss0;
        spart[(mg * 16 + lr + 8) * 4 + ng] = ss1;
    }
    __syncthreads();
    float s0 = spart[(mg * 16 + lr) * 4 + 0] + spart[(mg * 16 + lr) * 4 + 1]
             + spart[(mg * 16 + lr) * 4 + 2] + spart[(mg * 16 + lr) * 4 + 3];
    float s1 = spart[(mg * 16 + lr + 8) * 4 + 0] + spart[(mg * 16 + lr + 8) * 4 + 1]
             + spart[(mg * 16 + lr + 8) * 4 + 2] + spart[(mg * 16 + lr + 8) * 4 + 3];
    float inv0 = 1.f / fmaxf(sqrtf(s0), 1e-12f);
    float inv1 = 1.f / fmaxf(sqrtf(s1), 1e-12f);

    int node0 = row0 + mg * 16 + lr;
#pragma unroll
    for (int nt = 0; nt < 8; nt++) {
        int col = ng * 64 + nt * 8 + lc * 2;
        float z0 = d[0][nt][0] * inv0 + d[1][nt][0];
        float z1 = d[0][nt][1] * inv0 + d[1][nt][1];
        float z2 = d[0][nt][2] * inv1 + d[1][nt][2];
        float z3 = d[0][nt][3] * inv1 + d[1][nt][3];
        z0 = (z0 > 0.f) ? z0 : expm1f(z0);
        z1 = (z1 > 0.f) ? z1 : expm1f(z1);
        z2 = (z2 > 0.f) ? z2 : expm1f(z2);
        z3 = (z3 > 0.f) ? z3 : expm1f(z3);
        uint32_t hw, lw;
        split2(z0, z1, hw, lw);
        *(uint32_t*)(g_hhi + (size_t)node0 * HID + col) = hw;
        *(uint32_t*)(g_hlo + (size_t)node0 * HID + col) = lw;
        split2(z2, z3, hw, lw);
        *(uint32_t*)(g_hhi + (size_t)(node0 + 8) * HID + col) = hw;
        *(uint32_t*)(g_hlo + (size_t)(node0 + 8) * HID + col) = lw;
    }
}

// ---------------- launch 6: layer-2 GEMM via mma.sync bf16x3 ----------------------
__global__ __launch_bounds__(512, 1) void gemm2_kernel()
{
    extern __shared__ __align__(16) __nv_bfloat16 smem[];
    __nv_bfloat16* shh = smem;
    __nv_bfloat16* shw = smem + 2 * 128 * SW;

    int tid = threadIdx.x;
    int bt = blockIdx.x >> 1, bs = blockIdx.x & 1;
    int w = tid >> 5, lane = tid & 31;
    int mg = w & 3, ng = w >> 2;
    int lr = lane >> 2, lc = lane & 3;

    uint32_t shh_u = (uint32_t)__cvta_generic_to_shared(shh);
    uint32_t shw_u = (uint32_t)__cvta_generic_to_shared(shw);
    int ar = lane & 15, ak = (lane >> 4) * 8;
    uint32_t aoff[2][2];
#pragma unroll
    for (int hl = 0; hl < 2; hl++)
#pragma unroll
        for (int ms = 0; ms < 2; ms++)
            aoff[hl][ms] = shh_u +
                (uint32_t)(((hl * 128 + (mg * 2 + ms) * 16 + ar) * SW + ak) * 2);
    int bsel = lane >> 4, bw2 = lane & 15;
    int brow = bw2 & 7, bk = (bw2 >> 3) * 8;
    uint32_t boff[2];
#pragma unroll
    for (int hl = 0; hl < 2; hl++)
        boff[hl] = shw_u +
            (uint32_t)(((hl * 192 + (ng * 6 + bsel) * 8 + brow) * SW + bk) * 2);
    const uint32_t PRSTEP = 16 * SW * 2;

    float d[2][6][4];
#pragma unroll
    for (int ms = 0; ms < 2; ms++)
#pragma unroll
        for (int nt = 0; nt < 6; nt++)
#pragma unroll
            for (int j = 0; j < 4; j++) d[ms][nt][j] = 0.f;

    for (int kc = 0; kc < 8; kc++) {
#pragma unroll
        for (int i = tid; i < 2560; i += 512) {
            if (i < 1024) {
                int hl = i >> 9, r = (i & 511) >> 2, q = i & 3;
                const __nv_bfloat16* src = (hl ? g_hlo : g_hhi)
                    + ((size_t)(bt * 128 + r) << 8) + kc * 32;
                *(uint4*)(shh + (hl * 128 + r) * SW + q * 8) = ((const uint4*)src)[q];
            } else {
                int j = i - 1024;
                int hl = (j >= 768) ? 1 : 0, jj = j - hl * 768;
                int r = jj >> 2, q = jj & 3;
                const __nv_bfloat16* src = (hl ? g_w2lo : g_w2hi)
                    + ((size_t)(bs * 192 + r) << 8) + kc * 32;
                *(uint4*)(shw + (hl * 192 + r) * SW + q * 8) = ((const uint4*)src)[q];
            }
        }
        __syncthreads();

#pragma unroll
        for (int ks = 0; ks < 2; ks++) {
            uint32_t ka = ks * 32;
            uint32_t ah0[4], ah1[4], al0[4], al1[4];
            ldsm4(ah0, aoff[0][0] + ka);
            ldsm4(ah1, aoff[0][1] + ka);
            ldsm4(al0, aoff[1][0] + ka);
            ldsm4(al1, aoff[1][1] + ka);
#pragma unroll
            for (int pr = 0; pr < 3; pr++) {
                uint32_t bh[4], bl[4];
                ldsm4(bh, boff[0] + pr * PRSTEP + ka);
                ldsm4(bl, boff[1] + pr * PRSTEP + ka);
                int n0 = pr * 2, n1 = pr * 2 + 1;
                MMA_BF16(d[0][n0], ah0, bh[0], bh[1]);
                MMA_BF16(d[0][n0], ah0, bl[0], bl[1]);
                MMA_BF16(d[0][n0], al0, bh[0], bh[1]);
                MMA_BF16(d[1][n0], ah1, bh[0], bh[1]);
                MMA_BF16(d[1][n0], ah1, bl[0], bl[1]);
                MMA_BF16(d[1][n0], al1, bh[0], bh[1]);
                MMA_BF16(d[0][n1], ah0, bh[2], bh[3]);
                MMA_BF16(d[0][n1], ah0, bl[2], bl[3]);
                MMA_BF16(d[0][n1], al0, bh[2], bh[3]);
                MMA_BF16(d[1][n1], ah1, bh[2], bh[3]);
                MMA_BF16(d[1][n1], ah1, bl[2], bl[3]);
                MMA_BF16(d[1][n1], al1, bh[2], bh[3]);
            }
        }
        __syncthreads();
    }

#pragma unroll
    for (int ms = 0; ms < 2; ms++) {
#pragma unroll
        for (int nt = 0; nt < 6; nt++) {
            int node0 = bt * 128 + (mg * 2 + ms) * 16 + lr;
            int slot  = bs * 192 + (ng * 6 + nt) * 8 + lc * 2;
            if (node0 < NN)
                *(float2*)&g_prl[(size_t)node0 * PRLS + slot] =
                    make_float2(d[ms][nt][0], d[ms][nt][1]);
            if (node0 + 8 < NN)
                *(float2*)&g_prl[(size_t)(node0 + 8) * PRLS + slot] =
                    make_float2(d[ms][nt][2], d[ms][nt][3]);
        }
    }
}

// ---------------- launch 7: gather 2 + final epilogue + invariant restore ---------
__global__ __launch_bounds__(256) void gather2_final_kernel(
    const float* __restrict__ b2, const float* __restrict__ bl2,
    float* __restrict__ out)
{
    int t = blockIdx.x * blockDim.x + threadIdx.x;
    if (t == 0) g_base = 0;
    int n = t >> 5;
    if (n >= NN) return;
    int l = t & 31;
    int b = g_off[n], cnt = g_cnt[n], e2 = b + cnt;
    float invd = 1.f / fmaxf((float)cnt, 1.f);

    float4 a = make_float4(0.f, 0.f, 0.f, 0.f);
    int i = b;
    for (; i + 3 < e2; i += 4) {
        int s0 = g_adj[i], s1 = g_adj[i + 1], s2 = g_adj[i + 2], s3 = g_adj[i + 3];
        if (l < 31) {
            float4 v0 = *(const float4*)(g_prl + (size_t)s0 * PRLS + l * 4);
            float4 v1 = *(const float4*)(g_prl + (size_t)s1 * PRLS + l * 4);
            float4 v2 = *(const float4*)(g_prl + (size_t)s2 * PRLS + l * 4);
            float4 v3 = *(const float4*)(g_prl + (size_t)s3 * PRLS + l * 4);
            a.x += (v0.x + v1.x) + (v2.x + v3.x);
            a.y += (v0.y + v1.y) + (v2.y + v3.y);
            a.z += (v0.z + v1.z) + (v2.z + v3.z);
            a.w += (v0.w + v1.w) + (v2.w + v3.w);
        }
    }
    for (; i < e2; i++) {
        int s0 = g_adj[i];
        if (l < 31) {
            float4 v0 = *(const float4*)(g_prl + (size_t)s0 * PRLS + l * 4);
            a.x += v0.x; a.y += v0.y; a.z += v0.z; a.w += v0.w;
        }
    }
    if (l == 0) g_cnt[n] = 0;

    float4 tv = make_float4(0.f, 0.f, 0.f, 0.f);
    float4 l2v = make_float4(0.f, 0.f, 0.f, 0.f);
    int c = l * 4;
    if (l < 31) {
        float4 rr = *(const float4*)(g_prl + (size_t)n * PRLS + 128 + c);
        float4 ll = *(const float4*)(g_prl + (size_t)n * PRLS + 256 + c);
        float b0  = (c + 0 < NC) ? b2[c + 0] : 0.f;
        float bb1 = (c + 1 < NC) ? b2[c + 1] : 0.f;
        float bb2 = (c + 2 < NC) ? b2[c + 2] : 0.f;
        float b3  = (c + 3 < NC) ? b2[c + 3] : 0.f;
        tv.x = a.x * invd + b0  + rr.x;
        tv.y = a.y * invd + bb1 + rr.y;
        tv.z = a.z * invd + bb2 + rr.z;
        tv.w = a.w * invd + b3  + rr.w;
        l2v.x = ll.x + ((c + 0 < NC) ? bl2[c + 0] : 0.f);
        l2v.y = ll.y + ((c + 1 < NC) ? bl2[c + 1] : 0.f);
        l2v.z = ll.z + ((c + 2 < NC) ? bl2[c + 2] : 0.f);
        l2v.w = ll.w + ((c + 3 < NC) ? bl2[c + 3] : 0.f);
    }
    float s = tv.x*tv.x + tv.y*tv.y + tv.z*tv.z + tv.w*tv.w;
#pragma unroll
    for (int o = 16; o; o >>= 1) s += __shfl_xor_sync(0xffffffffu, s, o);
    float inv = 1.f / fmaxf(sqrtf(s), 1e-12f);

    float* orow = out + (size_t)n * NC;
    if (l < 30) {
        orow[c + 0] = tv.x * inv + l2v.x;
        orow[c + 1] = tv.y * inv + l2v.y;
        orow[c + 2] = tv.z * inv + l2v.z;
        orow[c + 3] = tv.w * inv + l2v.w;
    } else if (l == 30) {
        orow[120] = tv.x * inv + l2v.x;
    }
}

// ---------------- launcher ----------------------------------------------------------
extern "C" void kernel_launch(void* const* d_in, const int* in_sizes, int n_in,
                              void* d_out, int out_size)
{
    const float* x   = (const float*)d_in[0];
    const int*   ei  = (const int*)d_in[1];
    const float* w1l = (const float*)d_in[2];
    const float* b1  = (const float*)d_in[3];
    const float* w1r = (const float*)d_in[4];
    const float* wl1 = (const float*)d_in[5];
    const float* bl1 = (const float*)d_in[6];
    const float* w2l = (const float*)d_in[7];
    const float* b2  = (const float*)d_in[8];
    const float* w2r = (const float*)d_in[9];
    const float* wl2 = (const float*)d_in[10];
    const float* bl2 = (const float*)d_in[11];
    float* out = (float*)d_out;

    const int SMEM2 = (2 * 128 * SW + 2 * 192 * SW) * (int)sizeof(__nv_bfloat16);
    const int SMEM1 = (2 * 64 * ASW + 2 * 512 * SW) * (int)sizeof(__nv_bfloat16)
                    + 64 * 4 * (int)sizeof(float);
    cudaFuncSetAttribute(gemm2_kernel,
                         cudaFuncAttributeMaxDynamicSharedMemorySize, SMEM2);
    cudaFuncSetAttribute(gemm1_kernel,
                         cudaFuncAttributeMaxDynamicSharedMemorySize, SMEM1);

    histsetup_kernel   <<<(NE + 255) / 256, 256>>>(ei, w1l, w1r, wl1, w2l, w2r, wl2); // 1
    offsets_kernel     <<<(NN + 1023) / 1024, 1024>>>();                              // 2
    fill_kernel        <<<(NE + 255) / 256, 256>>>(ei);                               // 3
    gather1_kernel     <<<(NNP * 32 + 255) / 256, 256>>>(x);                          // 4 <- profiled
    gemm1_kernel       <<<NNP / 64, 512, SMEM1>>>(b1, bl1);                           // 5
    gemm2_kernel       <<<(NNP / 128) * 2, 512, SMEM2>>>();                           // 6
    gather2_final_kernel<<<(NN * 32 + 255) / 256, 256>>>(b2, bl2, out);               // 7
}

// round 16
// speedup vs baseline: 1.0990x; 1.0004x over previous
#include <cuda_runtime.h>
#include <cuda_bf16.h>
#include <cstdint>
#include <math.h>

#define NN   50000
#define NNP  50048
#define NE   800000
#define IND  50
#define HID  256
#define NC   121
#define PRLS 384
#define SW   40
#define ASW  136
#define C1   512
#define K1M  128

typedef unsigned long long u64;

// INVARIANT: g_cnt[] == 0 and g_base == 0 at kernel_launch entry (BSS + restore).
__device__ __align__(16) float g_prl [(size_t)NN * PRLS];
__device__ __align__(16) __nv_bfloat16 g_ahi[(size_t)NNP * K1M];
__device__ __align__(16) __nv_bfloat16 g_alo[(size_t)NNP * K1M];
__device__ __align__(16) __nv_bfloat16 g_hhi[(size_t)NNP * HID];
__device__ __align__(16) __nv_bfloat16 g_hlo[(size_t)NNP * HID];
__device__ __align__(16) __nv_bfloat16 g_w1hi[C1 * K1M];
__device__ __align__(16) __nv_bfloat16 g_w1lo[C1 * K1M];
__device__ __align__(16) __nv_bfloat16 g_w2hi[PRLS * HID];
__device__ __align__(16) __nv_bfloat16 g_w2lo[PRLS * HID];
__device__ int g_cnt[NN];
__device__ int g_off[NN];
__device__ int g_cur[NN];
__device__ int g_adj[NE];
__device__ int g_base;

#define MMA_BF16(D, A, B0, B1)                                               \
    asm volatile("mma.sync.aligned.m16n8k16.row.col.f32.bf16.bf16.f32 "      \
                 "{%0,%1,%2,%3},{%4,%5,%6,%7},{%8,%9},{%0,%1,%2,%3};"        \
                 : "+f"(D[0]), "+f"(D[1]), "+f"(D[2]), "+f"(D[3])            \
                 : "r"(A[0]), "r"(A[1]), "r"(A[2]), "r"(A[3]),               \
                   "r"(B0), "r"(B1))

__device__ __forceinline__ void ldsm4(uint32_t* r, uint32_t addr) {
    asm volatile("ldmatrix.sync.aligned.m8n8.x4.shared.b16 {%0,%1,%2,%3}, [%4];"
                 : "=r"(r[0]), "=r"(r[1]), "=r"(r[2]), "=r"(r[3]) : "r"(addr));
}

__device__ __forceinline__ void split2(float a, float b, uint32_t& hiw, uint32_t& low) {
    __nv_bfloat16 ha = __float2bfloat16(a), hb = __float2bfloat16(b);
    __nv_bfloat16 la = __float2bfloat16(a - __bfloat162float(ha));
    __nv_bfloat16 lb = __float2bfloat16(b - __bfloat162float(hb));
    __nv_bfloat162 H, L;
    H.x = ha; H.y = hb; L.x = la; L.y = lb;
    hiw = *(uint32_t*)&H; low = *(uint32_t*)&L;
}

// ---------------- launch 1: histogram + weight packing ---------------------------
__global__ __launch_bounds__(256) void histsetup_kernel(
    const int* __restrict__ ei,
    const float* __restrict__ w1l, const float* __restrict__ w1r,
    const float* __restrict__ wl1,
    const float* __restrict__ w2l, const float* __restrict__ w2r,
    const float* __restrict__ wl2)
{
    int t = blockIdx.x * blockDim.x + threadIdx.x;
    if (t < NE) atomicAdd(&g_cnt[ei[NE + t]], 1);
    if (t < C1 * K1M) {
        int col = t >> 7, k = t & 127;
        float val = 0.f;
        if (col < HID) {
            if (k < IND)          val = w1l[k * HID + col];
            else if (k < 2 * IND) val = w1r[(k - IND) * HID + col];
        } else {
            if (k >= IND && k < 2 * IND) val = wl1[(k - IND) * HID + (col - HID)];
        }
        __nv_bfloat16 h = __float2bfloat16(val);
        g_w1hi[t] = h;
        g_w1lo[t] = __float2bfloat16(val - __bfloat162float(h));
    }
    if (t < PRLS * 32) {
        int slot = t >> 5, k0 = (t & 31) * 8;
        int seg = slot >> 7, idx = slot & 127;
        const float* w = (seg == 0) ? w2l : (seg == 1) ? w2r : wl2;
        union { __nv_bfloat16 b[8]; uint4 v; } H, L;
#pragma unroll
        for (int j = 0; j < 8; j++) {
            float val = (idx < NC) ? w[(k0 + j) * NC + idx] : 0.f;
            __nv_bfloat16 h = __float2bfloat16(val);
            H.b[j] = h;
            L.b[j] = __float2bfloat16(val - __bfloat162float(h));
        }
        *(uint4*)(g_w2hi + (size_t)slot * HID + k0) = H.v;
        *(uint4*)(g_w2lo + (size_t)slot * HID + k0) = L.v;
    }
}

// ---------------- launch 2: order-free CSR offsets -------------------------------
__global__ __launch_bounds__(1024) void offsets_kernel() {
    __shared__ int ws[32];
    __shared__ int sbase;
    int i = blockIdx.x * 1024 + threadIdx.x;
    int lane = threadIdx.x & 31, wid = threadIdx.x >> 5;
    int c = (i < NN) ? g_cnt[i] : 0;
    int v = c;
#pragma unroll
    for (int o = 1; o < 32; o <<= 1) {
        int u = __shfl_up_sync(0xffffffffu, v, o);
        if (lane >= o) v += u;
    }
    if (lane == 31) ws[wid] = v;
    __syncthreads();
    if (wid == 0) {
        int w = ws[lane];
#pragma unroll
        for (int o = 1; o < 32; o <<= 1) {
            int u = __shfl_up_sync(0xffffffffu, w, o);
            if (lane >= o) w += u;
        }
        ws[lane] = w;
    }
    __syncthreads();
    int excl = v - c + (wid ? ws[wid - 1] : 0);
    if (threadIdx.x == 1023) sbase = atomicAdd(&g_base, excl + c);
    __syncthreads();
    if (i < NN) { int o = sbase + excl; g_off[i] = o; g_cur[i] = o; }
}

// ---------------- launch 3: fill adjacency ---------------------------------------
__global__ __launch_bounds__(256) void fill_kernel(const int* __restrict__ ei) {
    int e = blockIdx.x * blockDim.x + threadIdx.x;
    if (e >= NE) return;
    int pos = atomicAdd(&g_cur[ei[NE + e]], 1);
    g_adj[pos] = ei[e];
}

// ---------------- launch 4 (profiled): gather 1 -> bf16 hi/lo A rows --------------
__global__ __launch_bounds__(256) void gather1_kernel(const float* __restrict__ x) {
    int t = blockIdx.x * blockDim.x + threadIdx.x;
    int n = t >> 5;
    if (n >= NNP) return;
    int l = t & 31;
    bool valid = n < NN;
    int b = valid ? g_off[n] : 0, cnt = valid ? g_cnt[n] : 0, e2 = b + cnt;
    float inv = 1.f / fmaxf((float)cnt, 1.f);
    bool act = l < 25;
    float2 a = make_float2(0.f, 0.f);
    int i = b;
    for (; i + 3 < e2; i += 4) {
        int s0 = g_adj[i], s1 = g_adj[i + 1], s2 = g_adj[i + 2], s3 = g_adj[i + 3];
        if (act) {
            float2 v0 = *((const float2*)(x + (size_t)s0 * IND) + l);
            float2 v1 = *((const float2*)(x + (size_t)s1 * IND) + l);
            float2 v2 = *((const float2*)(x + (size_t)s2 * IND) + l);
            float2 v3 = *((const float2*)(x + (size_t)s3 * IND) + l);
            a.x += (v0.x + v1.x) + (v2.x + v3.x);
            a.y += (v0.y + v1.y) + (v2.y + v3.y);
        }
    }
    for (; i < e2; i++) {
        int s0 = g_adj[i];
        if (act) {
            float2 v0 = *((const float2*)(x + (size_t)s0 * IND) + l);
            a.x += v0.x; a.y += v0.y;
        }
    }
    __nv_bfloat16* ahi = g_ahi + (size_t)n * K1M;
    __nv_bfloat16* alo = g_alo + (size_t)n * K1M;
    if (act) {
        uint32_t hw, lw;
        split2(a.x * inv, a.y * inv, hw, lw);
        *(uint32_t*)(ahi + 2 * l) = hw;
        *(uint32_t*)(alo + 2 * l) = lw;
        float2 xv = valid ? *((const float2*)(x + (size_t)n * IND) + l)
                          : make_float2(0.f, 0.f);
        split2(xv.x, xv.y, hw, lw);
        *(uint32_t*)(ahi + 50 + 2 * l) = hw;
        *(uint32_t*)(alo + 50 + 2 * l) = lw;
    } else {
        int c0 = 100 + (l - 25) * 4;
        *(uint2*)(ahi + c0) = make_uint2(0u, 0u);
        *(uint2*)(alo + c0) = make_uint2(0u, 0u);
    }
}

// ---------------- launch 5: layer-1 MMA GEMM (interleaved schedule) ----------------
__global__ __launch_bounds__(512, 1) void gemm1_kernel(
    const float* __restrict__ b1, const float* __restrict__ bl1)
{
    extern __shared__ __align__(16) char smem1[];
    __nv_bfloat16* sA = (__nv_bfloat16*)smem1;            // [2][64][ASW]
    __nv_bfloat16* sB = sA + 2 * 64 * ASW;                // [2][512][SW]
    float* spart = (float*)(sB + 2 * 512 * SW);           // [64][4]

    int tid = threadIdx.x;
    int w = tid >> 5, lane = tid & 31;
    int row0 = blockIdx.x * 64;

#pragma unroll
    for (int i = tid; i < 2048; i += 512) {
        int hl = i >> 10, rem = i & 1023;
        int r = rem >> 4, q = rem & 15;
        const __nv_bfloat16* src = (hl ? g_alo : g_ahi)
            + (size_t)(row0 + r) * K1M + q * 8;
        *(uint4*)(sA + (hl * 64 + r) * ASW + q * 8) = *(const uint4*)src;
    }

    int mg = w >> 2, ng = w & 3;
    int lr = lane >> 2, lc = lane & 3;

    uint32_t sA_u = (uint32_t)__cvta_generic_to_shared(sA);
    uint32_t sB_u = (uint32_t)__cvta_generic_to_shared(sB);
    int ar = lane & 15, ak = (lane >> 4) * 8;
    uint32_t aoff[2];
#pragma unroll
    for (int hl = 0; hl < 2; hl++)
        aoff[hl] = sA_u + (uint32_t)(((hl * 64 + mg * 16 + ar) * ASW + ak) * 2);
    int bsel = lane >> 4, bw2 = lane & 15;
    int brow = bw2 & 7, bk = (bw2 >> 3) * 8;
    uint32_t boff[2][2];
#pragma unroll
    for (int hl = 0; hl < 2; hl++)
#pragma unroll
        for (int h = 0; h < 2; h++)
            boff[hl][h] = sB_u +
                (uint32_t)(((hl * 512 + h * 256 + ng * 64 + bsel * 8 + brow) * SW + bk) * 2);
    const uint32_t PRSTEP = 16 * SW * 2;

    float d[2][8][4];
#pragma unroll
    for (int h = 0; h < 2; h++)
#pragma unroll
        for (int nt = 0; nt < 8; nt++)
#pragma unroll
            for (int j = 0; j < 4; j++) d[h][nt][j] = 0.f;

    for (int kc = 0; kc < 4; kc++) {
#pragma unroll
        for (int i = tid; i < 4096; i += 512) {
            int hl = i >> 11, rem = i & 2047;
            int col = rem >> 2, q = rem & 3;
            const __nv_bfloat16* src = (hl ? g_w1lo : g_w1hi)
                + (size_t)col * K1M + kc * 32 + q * 8;
            *(uint4*)(sB + (hl * 512 + col) * SW + q * 8) = *(const uint4*)src;
        }
        __syncthreads();

#pragma unroll
        for (int ks = 0; ks < 2; ks++) {
            uint32_t ka = (uint32_t)((kc * 32 + ks * 16) * 2);
            uint32_t kb = (uint32_t)(ks * 32);
            uint32_t ah[4], al[4];
            ldsm4(ah, aoff[0] + ka);
            ldsm4(al, aoff[1] + ka);
#pragma unroll
            for (int h = 0; h < 2; h++) {
#pragma unroll
                for (int pp = 0; pp < 2; pp++) {     // pr pairs {0,1},{2,3}
                    int p0 = pp * 2, p1 = pp * 2 + 1;
                    uint32_t bhA[4], blA[4], bhB[4], blB[4];
                    ldsm4(bhA, boff[0][h] + p0 * PRSTEP + kb);
                    ldsm4(blA, boff[1][h] + p0 * PRSTEP + kb);
                    ldsm4(bhB, boff[0][h] + p1 * PRSTEP + kb);
                    ldsm4(blB, boff[1][h] + p1 * PRSTEP + kb);
                    float* t0 = d[h][p0 * 2];
                    float* t1 = d[h][p0 * 2 + 1];
                    float* t2 = d[h][p1 * 2];
                    float* t3 = d[h][p1 * 2 + 1];
                    // interleaved: same-accumulator reuse at distance 4
                    MMA_BF16(t0, ah, bhA[0], bhA[1]);
                    MMA_BF16(t1, ah, bhA[2], bhA[3]);
                    MMA_BF16(t2, ah, bhB[0], bhB[1]);
                    MMA_BF16(t3, ah, bhB[2], bhB[3]);
                    MMA_BF16(t0, ah, blA[0], blA[1]);
                    MMA_BF16(t1, ah, blA[2], blA[3]);
                    MMA_BF16(t2, ah, blB[0], blB[1]);
                    MMA_BF16(t3, ah, blB[2], blB[3]);
                    MMA_BF16(t0, al, bhA[0], bhA[1]);
                    MMA_BF16(t1, al, bhA[2], bhA[3]);
                    MMA_BF16(t2, al, bhB[0], bhB[1]);
                    MMA_BF16(t3, al, bhB[2], bhB[3]);
                }
            }
        }
        __syncthreads();
    }

    // Epilogue
#pragma unroll
    for (int nt = 0; nt < 8; nt++) {
        int col = ng * 64 + nt * 8 + lc * 2;
        float bb0 = b1[col], bb1v = b1[col + 1];
        float lb0 = bl1[col], lb1 = bl1[col + 1];
        d[0][nt][0] += bb0;  d[0][nt][1] += bb1v;
        d[0][nt][2] += bb0;  d[0][nt][3] += bb1v;
        d[1][nt][0] += lb0;  d[1][nt][1] += lb1;
        d[1][nt][2] += lb0;  d[1][nt][3] += lb1;
    }
    float ss0 = 0.f, ss1 = 0.f;
#pragma unroll
    for (int nt = 0; nt < 8; nt++) {
        ss0 += d[0][nt][0] * d[0][nt][0] + d[0][nt][1] * d[0][nt][1];
        ss1 += d[0][nt][2] * d[0][nt][2] + d[0][nt][3] * d[0][nt][3];
    }
    ss0 += __shfl_xor_sync(0xffffffffu, ss0, 1);
    ss0 += __shfl_xor_sync(0xffffffffu, ss0, 2);
    ss1 += __shfl_xor_sync(0xffffffffu, ss1, 1);
    ss1 += __shfl_xor_sync(0xffffffffu, ss1, 2);
    if (lc == 0) {
        spart[(mg * 16 + lr) * 4 + ng] = ss0;
        spart[(mg * 16 + lr + 8) * 4 + ng] = ss1;
    }
    __syncthreads();
    float s0 = spart[(mg * 16 + lr) * 4 + 0] + spart[(mg * 16 + lr) * 4 + 1]
             + spart[(mg * 16 + lr) * 4 + 2] + spart[(mg * 16 + lr) * 4 + 3];
    float s1 = spart[(mg * 16 + lr + 8) * 4 + 0] + spart[(mg * 16 + lr + 8) * 4 + 1]
             + spart[(mg * 16 + lr + 8) * 4 + 2] + spart[(mg * 16 + lr + 8) * 4 + 3];
    float inv0 = 1.f / fmaxf(sqrtf(s0), 1e-12f);
    float inv1 = 1.f / fmaxf(sqrtf(s1), 1e-12f);

    int node0 = row0 + mg * 16 + lr;
#pragma unroll
    for (int nt = 0; nt < 8; nt++) {
        int col = ng * 64 + nt * 8 + lc * 2;
        float z0 = d[0][nt][0] * inv0 + d[1][nt][0];
        float z1 = d[0][nt][1] * inv0 + d[1][nt][1];
        float z2 = d[0][nt][2] * inv1 + d[1][nt][2];
        float z3 = d[0][nt][3] * inv1 + d[1][nt][3];
        z0 = (z0 > 0.f) ? z0 : expm1f(z0);
        z1 = (z1 > 0.f) ? z1 : expm1f(z1);
        z2 = (z2 > 0.f) ? z2 : expm1f(z2);
        z3 = (z3 > 0.f) ? z3 : expm1f(z3);
        uint32_t hw, lw;
        split2(z0, z1, hw, lw);
        *(uint32_t*)(g_hhi + (size_t)node0 * HID + col) = hw;
        *(uint32_t*)(g_hlo + (size_t)node0 * HID + col) = lw;
        split2(z2, z3, hw, lw);
        *(uint32_t*)(g_hhi + (size_t)(node0 + 8) * HID + col) = hw;
        *(uint32_t*)(g_hlo + (size_t)(node0 + 8) * HID + col) = lw;
    }
}

// ---------------- launch 6: layer-2 GEMM (interleaved schedule) --------------------
__global__ __launch_bounds__(512, 1) void gemm2_kernel()
{
    extern __shared__ __align__(16) __nv_bfloat16 smem[];
    __nv_bfloat16* shh = smem;
    __nv_bfloat16* shw = smem + 2 * 128 * SW;

    int tid = threadIdx.x;
    int bt = blockIdx.x >> 1, bs = blockIdx.x & 1;
    int w = tid >> 5, lane = tid & 31;
    int mg = w & 3, ng = w >> 2;
    int lr = lane >> 2, lc = lane & 3;

    uint32_t shh_u = (uint32_t)__cvta_generic_to_shared(shh);
    uint32_t shw_u = (uint32_t)__cvta_generic_to_shared(shw);
    int ar = lane & 15, ak = (lane >> 4) * 8;
    uint32_t aoff[2][2];
#pragma unroll
    for (int hl = 0; hl < 2; hl++)
#pragma unroll
        for (int ms = 0; ms < 2; ms++)
            aoff[hl][ms] = shh_u +
                (uint32_t)(((hl * 128 + (mg * 2 + ms) * 16 + ar) * SW + ak) * 2);
    int bsel = lane >> 4, bw2 = lane & 15;
    int brow = bw2 & 7, bk = (bw2 >> 3) * 8;
    uint32_t boff[2];
#pragma unroll
    for (int hl = 0; hl < 2; hl++)
        boff[hl] = shw_u +
            (uint32_t)(((hl * 192 + (ng * 6 + bsel) * 8 + brow) * SW + bk) * 2);
    const uint32_t PRSTEP = 16 * SW * 2;

    float d[2][6][4];
#pragma unroll
    for (int ms = 0; ms < 2; ms++)
#pragma unroll
        for (int nt = 0; nt < 6; nt++)
#pragma unroll
            for (int j = 0; j < 4; j++) d[ms][nt][j] = 0.f;

    for (int kc = 0; kc < 8; kc++) {
#pragma unroll
        for (int i = tid; i < 2560; i += 512) {
            if (i < 1024) {
                int hl = i >> 9, r = (i & 511) >> 2, q = i & 3;
                const __nv_bfloat16* src = (hl ? g_hlo : g_hhi)
                    + ((size_t)(bt * 128 + r) << 8) + kc * 32;
                *(uint4*)(shh + (hl * 128 + r) * SW + q * 8) = ((const uint4*)src)[q];
            } else {
                int j = i - 1024;
                int hl = (j >= 768) ? 1 : 0, jj = j - hl * 768;
                int r = jj >> 2, q = jj & 3;
                const __nv_bfloat16* src = (hl ? g_w2lo : g_w2hi)
                    + ((size_t)(bs * 192 + r) << 8) + kc * 32;
                *(uint4*)(shw + (hl * 192 + r) * SW + q * 8) = ((const uint4*)src)[q];
            }
        }
        __syncthreads();

#pragma unroll
        for (int ks = 0; ks < 2; ks++) {
            uint32_t ka = ks * 32;
            uint32_t ah0[4], ah1[4], al0[4], al1[4];
            ldsm4(ah0, aoff[0][0] + ka);
            ldsm4(ah1, aoff[0][1] + ka);
            ldsm4(al0, aoff[1][0] + ka);
            ldsm4(al1, aoff[1][1] + ka);
#pragma unroll
            for (int pr = 0; pr < 3; pr++) {
                uint32_t bh[4], bl[4];
                ldsm4(bh, boff[0] + pr * PRSTEP + ka);
                ldsm4(bl, boff[1] + pr * PRSTEP + ka);
                int n0 = pr * 2, n1 = pr * 2 + 1;
                // interleaved: same-accumulator reuse at distance 4
                MMA_BF16(d[0][n0], ah0, bh[0], bh[1]);
                MMA_BF16(d[1][n0], ah1, bh[0], bh[1]);
                MMA_BF16(d[0][n1], ah0, bh[2], bh[3]);
                MMA_BF16(d[1][n1], ah1, bh[2], bh[3]);
                MMA_BF16(d[0][n0], ah0, bl[0], bl[1]);
                MMA_BF16(d[1][n0], ah1, bl[0], bl[1]);
                MMA_BF16(d[0][n1], ah0, bl[2], bl[3]);
                MMA_BF16(d[1][n1], ah1, bl[2], bl[3]);
                MMA_BF16(d[0][n0], al0, bh[0], bh[1]);
                MMA_BF16(d[1][n0], al1, bh[0], bh[1]);
                MMA_BF16(d[0][n1], al0, bh[2], bh[3]);
                MMA_BF16(d[1][n1], al1, bh[2], bh[3]);
            }
        }
        __syncthreads();
    }

#pragma unroll
    for (int ms = 0; ms < 2; ms++) {
#pragma unroll
        for (int nt = 0; nt < 6; nt++) {
            int node0 = bt * 128 + (mg * 2 + ms) * 16 + lr;
            int slot  = bs * 192 + (ng * 6 + nt) * 8 + lc * 2;
            if (node0 < NN)
                *(float2*)&g_prl[(size_t)node0 * PRLS + slot] =
                    make_float2(d[ms][nt][0], d[ms][nt][1]);
            if (node0 + 8 < NN)
                *(float2*)&g_prl[(size_t)(node0 + 8) * PRLS + slot] =
                    make_float2(d[ms][nt][2], d[ms][nt][3]);
        }
    }
}

// ---------------- launch 7: gather 2 + final epilogue + invariant restore ---------
__global__ __launch_bounds__(256) void gather2_final_kernel(
    const float* __restrict__ b2, const float* __restrict__ bl2,
    float* __restrict__ out)
{
    int t = blockIdx.x * blockDim.x + threadIdx.x;
    if (t == 0) g_base = 0;
    int n = t >> 5;
    if (n >= NN) return;
    int l = t & 31;
    int b = g_off[n], cnt = g_cnt[n], e2 = b + cnt;
    float invd = 1.f / fmaxf((float)cnt, 1.f);

    float4 a = make_float4(0.f, 0.f, 0.f, 0.f);
    int i = b;
    for (; i + 3 < e2; i += 4) {
        int s0 = g_adj[i], s1 = g_adj[i + 1], s2 = g_adj[i + 2], s3 = g_adj[i + 3];
        if (l < 31) {
            float4 v0 = *(const float4*)(g_prl + (size_t)s0 * PRLS + l * 4);
            float4 v1 = *(const float4*)(g_prl + (size_t)s1 * PRLS + l * 4);
            float4 v2 = *(const float4*)(g_prl + (size_t)s2 * PRLS + l * 4);
            float4 v3 = *(const float4*)(g_prl + (size_t)s3 * PRLS + l * 4);
            a.x += (v0.x + v1.x) + (v2.x + v3.x);
            a.y += (v0.y + v1.y) + (v2.y + v3.y);
            a.z += (v0.z + v1.z) + (v2.z + v3.z);
            a.w += (v0.w + v1.w) + (v2.w + v3.w);
        }
    }
    for (; i < e2; i++) {
        int s0 = g_adj[i];
        if (l < 31) {
            float4 v0 = *(const float4*)(g_prl + (size_t)s0 * PRLS + l * 4);
            a.x += v0.x; a.y += v0.y; a.z += v0.z; a.w += v0.w;
        }
    }
    if (l == 0) g_cnt[n] = 0;

    float4 tv = make_float4(0.f, 0.f, 0.f, 0.f);
    float4 l2v = make_float4(0.f, 0.f, 0.f, 0.f);
    int c = l * 4;
    if (l < 31) {
        float4 rr = *(const float4*)(g_prl + (size_t)n * PRLS + 128 + c);
        float4 ll = *(const float4*)(g_prl + (size_t)n * PRLS + 256 + c);
        float b0  = (c + 0 < NC) ? b2[c + 0] : 0.f;
        float bb1 = (c + 1 < NC) ? b2[c + 1] : 0.f;
        float bb2 = (c + 2 < NC) ? b2[c + 2] : 0.f;
        float b3  = (c + 3 < NC) ? b2[c + 3] : 0.f;
        tv.x = a.x * invd + b0  + rr.x;
        tv.y = a.y * invd + bb1 + rr.y;
        tv.z = a.z * invd + bb2 + rr.z;
        tv.w = a.w * invd + b3  + rr.w;
        l2v.x = ll.x + ((c + 0 < NC) ? bl2[c + 0] : 0.f);
        l2v.y = ll.y + ((c + 1 < NC) ? bl2[c + 1] : 0.f);
        l2v.z = ll.z + ((c + 2 < NC) ? bl2[c + 2] : 0.f);
        l2v.w = ll.w + ((c + 3 < NC) ? bl2[c + 3] : 0.f);
    }
    float s = tv.x*tv.x + tv.y*tv.y + tv.z*tv.z + tv.w*tv.w;
#pragma unroll
    for (int o = 16; o; o >>= 1) s += __shfl_xor_sync(0xffffffffu, s, o);
    float inv = 1.f / fmaxf(sqrtf(s), 1e-12f);

    float* orow = out + (size_t)n * NC;
    if (l < 30) {
        orow[c + 0] = tv.x * inv + l2v.x;
        orow[c + 1] = tv.y * inv + l2v.y;
        orow[c + 2] = tv.z * inv + l2v.z;
        orow[c + 3] = tv.w * inv + l2v.w;
    } else if (l == 30) {
        orow[120] = tv.x * inv + l2v.x;
    }
}

// ---------------- launcher ----------------------------------------------------------
extern "C" void kernel_launch(void* const* d_in, const int* in_sizes, int n_in,
                              void* d_out, int out_size)
{
    const float* x   = (const float*)d_in[0];
    const int*   ei  = (const int*)d_in[1];
    const float* w1l = (const float*)d_in[2];
    const float* b1  = (const float*)d_in[3];
    const float* w1r = (const float*)d_in[4];
    const float* wl1 = (const float*)d_in[5];
    const float* bl1 = (const float*)d_in[6];
    const float* w2l = (const float*)d_in[7];
    const float* b2  = (const float*)d_in[8];
    const float* w2r = (const float*)d_in[9];
    const float* wl2 = (const float*)d_in[10];
    const float* bl2 = (const float*)d_in[11];
    float* out = (float*)d_out;

    const int SMEM2 = (2 * 128 * SW + 2 * 192 * SW) * (int)sizeof(__nv_bfloat16);
    const int SMEM1 = (2 * 64 * ASW + 2 * 512 * SW) * (int)sizeof(__nv_bfloat16)
                    + 64 * 4 * (int)sizeof(float);
    cudaFuncSetAttribute(gemm2_kernel,
                         cudaFuncAttributeMaxDynamicSharedMemorySize, SMEM2);
    cudaFuncSetAttribute(gemm1_kernel,
                         cudaFuncAttributeMaxDynamicSharedMemorySize, SMEM1);

    histsetup_kernel   <<<(NE + 255) / 256, 256>>>(ei, w1l, w1r, wl1, w2l, w2r, wl2); // 1
    offsets_kernel     <<<(NN + 1023) / 1024, 1024>>>();                              // 2
    fill_kernel        <<<(NE + 255) / 256, 256>>>(ei);                               // 3
    gather1_kernel     <<<(NNP * 32 + 255) / 256, 256>>>(x);                          // 4 <- profiled
    gemm1_kernel       <<<NNP / 64, 512, SMEM1>>>(b1, bl1);                           // 5
    gemm2_kernel       <<<(NNP / 128) * 2, 512, SMEM2>>>();                           // 6
    gather2_final_kernel<<<(NN * 32 + 255) / 256, 256>>>(b2, bl2, out);               // 7
}

// round 17
// speedup vs baseline: 1.2902x; 1.1740x over previous
#include <cuda_runtime.h>
#include <cuda_fp16.h>
#include <cstdint>
#include <math.h>

#define NN   50000
#define NNP  50048
#define NE   800000
#define IND  50
#define HID  256
#define NC   121
#define PRLS 384
#define SW   40
#define ASW  136
#define C1   512
#define K1M  128

typedef unsigned long long u64;

// INVARIANT: g_cnt[] == 0 and g_base == 0 at kernel_launch entry (BSS + restore).
__device__ __align__(16) float g_prl [(size_t)NN * PRLS];
__device__ __align__(16) __half g_a  [(size_t)NNP * K1M];   // A rows: mean|x|0 (fp16)
__device__ __align__(16) __half g_h  [(size_t)NNP * HID];   // H (fp16)
__device__ __align__(16) __half g_w1hi[C1 * K1M];           // layer-1 W hi/lo (fp16 split)
__device__ __align__(16) __half g_w1lo[C1 * K1M];
__device__ __align__(16) __half g_w2hi[PRLS * HID];
__device__ __align__(16) __half g_w2lo[PRLS * HID];
__device__ int g_cnt[NN];
__device__ int g_off[NN];
__device__ int g_cur[NN];
__device__ int g_adj[NE];
__device__ int g_base;

#define MMA_F16(D, A, B0, B1)                                                \
    asm volatile("mma.sync.aligned.m16n8k16.row.col.f32.f16.f16.f32 "        \
                 "{%0,%1,%2,%3},{%4,%5,%6,%7},{%8,%9},{%0,%1,%2,%3};"        \
                 : "+f"(D[0]), "+f"(D[1]), "+f"(D[2]), "+f"(D[3])            \
                 : "r"(A[0]), "r"(A[1]), "r"(A[2]), "r"(A[3]),               \
                   "r"(B0), "r"(B1))

__device__ __forceinline__ void ldsm4(uint32_t* r, uint32_t addr) {
    asm volatile("ldmatrix.sync.aligned.m8n8.x4.shared.b16 {%0,%1,%2,%3}, [%4];"
                 : "=r"(r[0]), "=r"(r[1]), "=r"(r[2]), "=r"(r[3]) : "r"(addr));
}

__device__ __forceinline__ uint32_t pk2h(float a, float b) {
    __half2 h = __floats2half2_rn(a, b);
    return *(uint32_t*)&h;
}

// ---------------- launch 1: histogram + weight packing (fp16 hi/lo) --------------
__global__ __launch_bounds__(256) void histsetup_kernel(
    const int* __restrict__ ei,
    const float* __restrict__ w1l, const float* __restrict__ w1r,
    const float* __restrict__ wl1,
    const float* __restrict__ w2l, const float* __restrict__ w2r,
    const float* __restrict__ wl2)
{
    int t = blockIdx.x * blockDim.x + threadIdx.x;
    if (t < NE) atomicAdd(&g_cnt[ei[NE + t]], 1);
    if (t < C1 * K1M) {
        int col = t >> 7, k = t & 127;
        float val = 0.f;
        if (col < HID) {
            if (k < IND)          val = w1l[k * HID + col];
            else if (k < 2 * IND) val = w1r[(k - IND) * HID + col];
        } else {
            if (k >= IND && k < 2 * IND) val = wl1[(k - IND) * HID + (col - HID)];
        }
        __half h = __float2half(val);
        g_w1hi[t] = h;
        g_w1lo[t] = __float2half(val - __half2float(h));
    }
    if (t < PRLS * 32) {
        int slot = t >> 5, k0 = (t & 31) * 8;
        int seg = slot >> 7, idx = slot & 127;
        const float* w = (seg == 0) ? w2l : (seg == 1) ? w2r : wl2;
        union { __half b[8]; uint4 v; } H, L;
#pragma unroll
        for (int j = 0; j < 8; j++) {
            float val = (idx < NC) ? w[(k0 + j) * NC + idx] : 0.f;
            __half h = __float2half(val);
            H.b[j] = h;
            L.b[j] = __float2half(val - __half2float(h));
        }
        *(uint4*)(g_w2hi + (size_t)slot * HID + k0) = H.v;
        *(uint4*)(g_w2lo + (size_t)slot * HID + k0) = L.v;
    }
}

// ---------------- launch 2: order-free CSR offsets -------------------------------
__global__ __launch_bounds__(1024) void offsets_kernel() {
    __shared__ int ws[32];
    __shared__ int sbase;
    int i = blockIdx.x * 1024 + threadIdx.x;
    int lane = threadIdx.x & 31, wid = threadIdx.x >> 5;
    int c = (i < NN) ? g_cnt[i] : 0;
    int v = c;
#pragma unroll
    for (int o = 1; o < 32; o <<= 1) {
        int u = __shfl_up_sync(0xffffffffu, v, o);
        if (lane >= o) v += u;
    }
    if (lane == 31) ws[wid] = v;
    __syncthreads();
    if (wid == 0) {
        int w = ws[lane];
#pragma unroll
        for (int o = 1; o < 32; o <<= 1) {
            int u = __shfl_up_sync(0xffffffffu, w, o);
            if (lane >= o) w += u;
        }
        ws[lane] = w;
    }
    __syncthreads();
    int excl = v - c + (wid ? ws[wid - 1] : 0);
    if (threadIdx.x == 1023) sbase = atomicAdd(&g_base, excl + c);
    __syncthreads();
    if (i < NN) { int o = sbase + excl; g_off[i] = o; g_cur[i] = o; }
}

// ---------------- launch 3: fill adjacency ---------------------------------------
__global__ __launch_bounds__(256) void fill_kernel(const int* __restrict__ ei) {
    int e = blockIdx.x * blockDim.x + threadIdx.x;
    if (e >= NE) return;
    int pos = atomicAdd(&g_cur[ei[NE + e]], 1);
    g_adj[pos] = ei[e];
}

// ---------------- launch 4 (profiled): gather 1 -> fp16 A rows --------------------
__global__ __launch_bounds__(256) void gather1_kernel(const float* __restrict__ x) {
    int t = blockIdx.x * blockDim.x + threadIdx.x;
    int n = t >> 5;
    if (n >= NNP) return;
    int l = t & 31;
    bool valid = n < NN;
    int b = valid ? g_off[n] : 0, cnt = valid ? g_cnt[n] : 0, e2 = b + cnt;
    float inv = 1.f / fmaxf((float)cnt, 1.f);
    bool act = l < 25;
    float2 a = make_float2(0.f, 0.f);
    int i = b;
    for (; i + 3 < e2; i += 4) {
        int s0 = g_adj[i], s1 = g_adj[i + 1], s2 = g_adj[i + 2], s3 = g_adj[i + 3];
        if (act) {
            float2 v0 = *((const float2*)(x + (size_t)s0 * IND) + l);
            float2 v1 = *((const float2*)(x + (size_t)s1 * IND) + l);
            float2 v2 = *((const float2*)(x + (size_t)s2 * IND) + l);
            float2 v3 = *((const float2*)(x + (size_t)s3 * IND) + l);
            a.x += (v0.x + v1.x) + (v2.x + v3.x);
            a.y += (v0.y + v1.y) + (v2.y + v3.y);
        }
    }
    for (; i < e2; i++) {
        int s0 = g_adj[i];
        if (act) {
            float2 v0 = *((const float2*)(x + (size_t)s0 * IND) + l);
            a.x += v0.x; a.y += v0.y;
        }
    }
    __half* ar = g_a + (size_t)n * K1M;
    if (act) {
        *(uint32_t*)(ar + 2 * l) = pk2h(a.x * inv, a.y * inv);
        float2 xv = valid ? *((const float2*)(x + (size_t)n * IND) + l)
                          : make_float2(0.f, 0.f);
        *(uint32_t*)(ar + 50 + 2 * l) = pk2h(xv.x, xv.y);
    } else {
        int c0 = 100 + (l - 25) * 4;
        *(uint2*)(ar + c0) = make_uint2(0u, 0u);
    }
}

// ---------------- launch 5: layer-1 MMA GEMM (fp16x2) + bias + norm + ELU ---------
__global__ __launch_bounds__(512, 1) void gemm1_kernel(
    const float* __restrict__ b1, const float* __restrict__ bl1)
{
    extern __shared__ __align__(16) char smem1[];
    __half* sA = (__half*)smem1;               // [64][ASW]
    __half* sB = sA + 64 * ASW;                // [2][512][SW]
    float* spart = (float*)(sB + 2 * 512 * SW);// [64][4]

    int tid = threadIdx.x;
    int w = tid >> 5, lane = tid & 31;
    int row0 = blockIdx.x * 64;

#pragma unroll
    for (int i = tid; i < 1024; i += 512) {
        int r = i >> 4, q = i & 15;
        const __half* src = g_a + (size_t)(row0 + r) * K1M + q * 8;
        *(uint4*)(sA + r * ASW + q * 8) = *(const uint4*)src;
    }

    int mg = w >> 2, ng = w & 3;
    int lr = lane >> 2, lc = lane & 3;

    uint32_t sA_u = (uint32_t)__cvta_generic_to_shared(sA);
    uint32_t sB_u = (uint32_t)__cvta_generic_to_shared(sB);
    int arr = lane & 15, ak = (lane >> 4) * 8;
    uint32_t aoff = sA_u + (uint32_t)(((mg * 16 + arr) * ASW + ak) * 2);
    int bsel = lane >> 4, bw2 = lane & 15;
    int brow = bw2 & 7, bk = (bw2 >> 3) * 8;
    uint32_t boff[2][2];
#pragma unroll
    for (int hl = 0; hl < 2; hl++)
#pragma unroll
        for (int h = 0; h < 2; h++)
            boff[hl][h] = sB_u +
                (uint32_t)(((hl * 512 + h * 256 + ng * 64 + bsel * 8 + brow) * SW + bk) * 2);
    const uint32_t PRSTEP = 16 * SW * 2;

    float d[2][8][4];
#pragma unroll
    for (int h = 0; h < 2; h++)
#pragma unroll
        for (int nt = 0; nt < 8; nt++)
#pragma unroll
            for (int j = 0; j < 4; j++) d[h][nt][j] = 0.f;

    for (int kc = 0; kc < 4; kc++) {
#pragma unroll
        for (int i = tid; i < 4096; i += 512) {
            int hl = i >> 11, rem = i & 2047;
            int col = rem >> 2, q = rem & 3;
            const __half* src = (hl ? g_w1lo : g_w1hi)
                + (size_t)col * K1M + kc * 32 + q * 8;
            *(uint4*)(sB + (hl * 512 + col) * SW + q * 8) = *(const uint4*)src;
        }
        __syncthreads();

#pragma unroll
        for (int ks = 0; ks < 2; ks++) {
            uint32_t ka = (uint32_t)((kc * 32 + ks * 16) * 2);
            uint32_t kb = (uint32_t)(ks * 32);
            uint32_t ah[4];
            ldsm4(ah, aoff + ka);
#pragma unroll
            for (int h = 0; h < 2; h++) {
#pragma unroll
                for (int pp = 0; pp < 2; pp++) {
                    int p0 = pp * 2, p1 = pp * 2 + 1;
                    uint32_t bhA[4], blA[4], bhB[4], blB[4];
                    ldsm4(bhA, boff[0][h] + p0 * PRSTEP + kb);
                    ldsm4(blA, boff[1][h] + p0 * PRSTEP + kb);
                    ldsm4(bhB, boff[0][h] + p1 * PRSTEP + kb);
                    ldsm4(blB, boff[1][h] + p1 * PRSTEP + kb);
                    float* t0 = d[h][p0 * 2];
                    float* t1 = d[h][p0 * 2 + 1];
                    float* t2 = d[h][p1 * 2];
                    float* t3 = d[h][p1 * 2 + 1];
                    MMA_F16(t0, ah, bhA[0], bhA[1]);
                    MMA_F16(t1, ah, bhA[2], bhA[3]);
                    MMA_F16(t2, ah, bhB[0], bhB[1]);
                    MMA_F16(t3, ah, bhB[2], bhB[3]);
                    MMA_F16(t0, ah, blA[0], blA[1]);
                    MMA_F16(t1, ah, blA[2], blA[3]);
                    MMA_F16(t2, ah, blB[0], blB[1]);
                    MMA_F16(t3, ah, blB[2], blB[3]);
                }
            }
        }
        __syncthreads();
    }

    // Epilogue: bias, L2 norm over acc, z = acc*inv + lin, ELU, fp16 out
#pragma unroll
    for (int nt = 0; nt < 8; nt++) {
        int col = ng * 64 + nt * 8 + lc * 2;
        float bb0 = b1[col], bb1v = b1[col + 1];
        float lb0 = bl1[col], lb1 = bl1[col + 1];
        d[0][nt][0] += bb0;  d[0][nt][1] += bb1v;
        d[0][nt][2] += bb0;  d[0][nt][3] += bb1v;
        d[1][nt][0] += lb0;  d[1][nt][1] += lb1;
        d[1][nt][2] += lb0;  d[1][nt][3] += lb1;
    }
    float ss0 = 0.f, ss1 = 0.f;
#pragma unroll
    for (int nt = 0; nt < 8; nt++) {
        ss0 += d[0][nt][0] * d[0][nt][0] + d[0][nt][1] * d[0][nt][1];
        ss1 += d[0][nt][2] * d[0][nt][2] + d[0][nt][3] * d[0][nt][3];
    }
    ss0 += __shfl_xor_sync(0xffffffffu, ss0, 1);
    ss0 += __shfl_xor_sync(0xffffffffu, ss0, 2);
    ss1 += __shfl_xor_sync(0xffffffffu, ss1, 1);
    ss1 += __shfl_xor_sync(0xffffffffu, ss1, 2);
    if (lc == 0) {
        spart[(mg * 16 + lr) * 4 + ng] = ss0;
        spart[(mg * 16 + lr + 8) * 4 + ng] = ss1;
    }
    __syncthreads();
    float s0 = spart[(mg * 16 + lr) * 4 + 0] + spart[(mg * 16 + lr) * 4 + 1]
             + spart[(mg * 16 + lr) * 4 + 2] + spart[(mg * 16 + lr) * 4 + 3];
    float s1 = spart[(mg * 16 + lr + 8) * 4 + 0] + spart[(mg * 16 + lr + 8) * 4 + 1]
             + spart[(mg * 16 + lr + 8) * 4 + 2] + spart[(mg * 16 + lr + 8) * 4 + 3];
    float inv0 = 1.f / fmaxf(sqrtf(s0), 1e-12f);
    float inv1 = 1.f / fmaxf(sqrtf(s1), 1e-12f);

    int node0 = row0 + mg * 16 + lr;
#pragma unroll
    for (int nt = 0; nt < 8; nt++) {
        int col = ng * 64 + nt * 8 + lc * 2;
        float z0 = d[0][nt][0] * inv0 + d[1][nt][0];
        float z1 = d[0][nt][1] * inv0 + d[1][nt][1];
        float z2 = d[0][nt][2] * inv1 + d[1][nt][2];
        float z3 = d[0][nt][3] * inv1 + d[1][nt][3];
        z0 = (z0 > 0.f) ? z0 : expm1f(z0);
        z1 = (z1 > 0.f) ? z1 : expm1f(z1);
        z2 = (z2 > 0.f) ? z2 : expm1f(z2);
        z3 = (z3 > 0.f) ? z3 : expm1f(z3);
        *(uint32_t*)(g_h + (size_t)node0 * HID + col) = pk2h(z0, z1);
        *(uint32_t*)(g_h + (size_t)(node0 + 8) * HID + col) = pk2h(z2, z3);
    }
}

// ---------------- launch 6: layer-2 GEMM (fp16x2) ---------------------------------
__global__ __launch_bounds__(512, 1) void gemm2_kernel()
{
    extern __shared__ __align__(16) __half smem[];
    __half* shh = smem;                  // [128][SW]
    __half* shw = smem + 128 * SW;       // [2][192][SW]

    int tid = threadIdx.x;
    int bt = blockIdx.x >> 1, bs = blockIdx.x & 1;
    int w = tid >> 5, lane = tid & 31;
    int mg = w & 3, ng = w >> 2;
    int lr = lane >> 2, lc = lane & 3;

    uint32_t shh_u = (uint32_t)__cvta_generic_to_shared(shh);
    uint32_t shw_u = (uint32_t)__cvta_generic_to_shared(shw);
    int arr = lane & 15, ak = (lane >> 4) * 8;
    uint32_t aoff[2];
#pragma unroll
    for (int ms = 0; ms < 2; ms++)
        aoff[ms] = shh_u +
            (uint32_t)((((mg * 2 + ms) * 16 + arr) * SW + ak) * 2);
    int bsel = lane >> 4, bw2 = lane & 15;
    int brow = bw2 & 7, bk = (bw2 >> 3) * 8;
    uint32_t boff[2];
#pragma unroll
    for (int hl = 0; hl < 2; hl++)
        boff[hl] = shw_u +
            (uint32_t)(((hl * 192 + (ng * 6 + bsel) * 8 + brow) * SW + bk) * 2);
    const uint32_t PRSTEP = 16 * SW * 2;

    float d[2][6][4];
#pragma unroll
    for (int ms = 0; ms < 2; ms++)
#pragma unroll
        for (int nt = 0; nt < 6; nt++)
#pragma unroll
            for (int j = 0; j < 4; j++) d[ms][nt][j] = 0.f;

    for (int kc = 0; kc < 8; kc++) {
#pragma unroll
        for (int i = tid; i < 2048; i += 512) {
            if (i < 512) {
                int r = i >> 2, q = i & 3;
                const __half* src = g_h + ((size_t)(bt * 128 + r) << 8) + kc * 32;
                *(uint4*)(shh + r * SW + q * 8) = ((const uint4*)src)[q];
            } else {
                int j = i - 512;
                int hl = (j >= 768) ? 1 : 0, jj = j - hl * 768;
                int r = jj >> 2, q = jj & 3;
                const __half* src = (hl ? g_w2lo : g_w2hi)
                    + ((size_t)(bs * 192 + r) << 8) + kc * 32;
                *(uint4*)(shw + (hl * 192 + r) * SW + q * 8) = ((const uint4*)src)[q];
            }
        }
        __syncthreads();

#pragma unroll
        for (int ks = 0; ks < 2; ks++) {
            uint32_t ka = ks * 32;
            uint32_t ah0[4], ah1[4];
            ldsm4(ah0, aoff[0] + ka);
            ldsm4(ah1, aoff[1] + ka);
#pragma unroll
            for (int pr = 0; pr < 3; pr++) {
                uint32_t bh[4], bl[4];
                ldsm4(bh, boff[0] + pr * PRSTEP + ka);
                ldsm4(bl, boff[1] + pr * PRSTEP + ka);
                int n0 = pr * 2, n1 = pr * 2 + 1;
                MMA_F16(d[0][n0], ah0, bh[0], bh[1]);
                MMA_F16(d[1][n0], ah1, bh[0], bh[1]);
                MMA_F16(d[0][n1], ah0, bh[2], bh[3]);
                MMA_F16(d[1][n1], ah1, bh[2], bh[3]);
                MMA_F16(d[0][n0], ah0, bl[0], bl[1]);
                MMA_F16(d[1][n0], ah1, bl[0], bl[1]);
                MMA_F16(d[0][n1], ah0, bl[2], bl[3]);
                MMA_F16(d[1][n1], ah1, bl[2], bl[3]);
            }
        }
        __syncthreads();
    }

#pragma unroll
    for (int ms = 0; ms < 2; ms++) {
#pragma unroll
        for (int nt = 0; nt < 6; nt++) {
            int node0 = bt * 128 + (mg * 2 + ms) * 16 + lr;
            int slot  = bs * 192 + (ng * 6 + nt) * 8 + lc * 2;
            if (node0 < NN)
                *(float2*)&g_prl[(size_t)node0 * PRLS + slot] =
                    make_float2(d[ms][nt][0], d[ms][nt][1]);
            if (node0 + 8 < NN)
                *(float2*)&g_prl[(size_t)(node0 + 8) * PRLS + slot] =
                    make_float2(d[ms][nt][2], d[ms][nt][3]);
        }
    }
}

// ---------------- launch 7: gather 2 + final epilogue + invariant restore ---------
__global__ __launch_bounds__(256) void gather2_final_kernel(
    const float* __restrict__ b2, const float* __restrict__ bl2,
    float* __restrict__ out)
{
    int t = blockIdx.x * blockDim.x + threadIdx.x;
    if (t == 0) g_base = 0;
    int n = t >> 5;
    if (n >= NN) return;
    int l = t & 31;
    int b = g_off[n], cnt = g_cnt[n], e2 = b + cnt;
    float invd = 1.f / fmaxf((float)cnt, 1.f);

    float4 a = make_float4(0.f, 0.f, 0.f, 0.f);
    int i = b;
    for (; i + 3 < e2; i += 4) {
        int s0 = g_adj[i], s1 = g_adj[i + 1], s2 = g_adj[i + 2], s3 = g_adj[i + 3];
        if (l < 31) {
            float4 v0 = *(const float4*)(g_prl + (size_t)s0 * PRLS + l * 4);
            float4 v1 = *(const float4*)(g_prl + (size_t)s1 * PRLS + l * 4);
            float4 v2 = *(const float4*)(g_prl + (size_t)s2 * PRLS + l * 4);
            float4 v3 = *(const float4*)(g_prl + (size_t)s3 * PRLS + l * 4);
            a.x += (v0.x + v1.x) + (v2.x + v3.x);
            a.y += (v0.y + v1.y) + (v2.y + v3.y);
            a.z += (v0.z + v1.z) + (v2.z + v3.z);
            a.w += (v0.w + v1.w) + (v2.w + v3.w);
        }
    }
    for (; i < e2; i++) {
        int s0 = g_adj[i];
        if (l < 31) {
            float4 v0 = *(const float4*)(g_prl + (size_t)s0 * PRLS + l * 4);
            a.x += v0.x; a.y += v0.y; a.z += v0.z; a.w += v0.w;
        }
    }
    if (l == 0) g_cnt[n] = 0;

    float4 tv = make_float4(0.f, 0.f, 0.f, 0.f);
    float4 l2v = make_float4(0.f, 0.f, 0.f, 0.f);
    int c = l * 4;
    if (l < 31) {
        float4 rr = *(const float4*)(g_prl + (size_t)n * PRLS + 128 + c);
        float4 ll = *(const float4*)(g_prl + (size_t)n * PRLS + 256 + c);
        float b0  = (c + 0 < NC) ? b2[c + 0] : 0.f;
        float bb1 = (c + 1 < NC) ? b2[c + 1] : 0.f;
        float bb2 = (c + 2 < NC) ? b2[c + 2] : 0.f;
        float b3  = (c + 3 < NC) ? b2[c + 3] : 0.f;
        tv.x = a.x * invd + b0  + rr.x;
        tv.y = a.y * invd + bb1 + rr.y;
        tv.z = a.z * invd + bb2 + rr.z;
        tv.w = a.w * invd + b3  + rr.w;
        l2v.x = ll.x + ((c + 0 < NC) ? bl2[c + 0] : 0.f);
        l2v.y = ll.y + ((c + 1 < NC) ? bl2[c + 1] : 0.f);
        l2v.z = ll.z + ((c + 2 < NC) ? bl2[c + 2] : 0.f);
        l2v.w = ll.w + ((c + 3 < NC) ? bl2[c + 3] : 0.f);
    }
    float s = tv.x*tv.x + tv.y*tv.y + tv.z*tv.z + tv.w*tv.w;
#pragma unroll
    for (int o = 16; o; o >>= 1) s += __shfl_xor_sync(0xffffffffu, s, o);
    float inv = 1.f / fmaxf(sqrtf(s), 1e-12f);

    float* orow = out + (size_t)n * NC;
    if (l < 30) {
        orow[c + 0] = tv.x * inv + l2v.x;
        orow[c + 1] = tv.y * inv + l2v.y;
        orow[c + 2] = tv.z * inv + l2v.z;
        orow[c + 3] = tv.w * inv + l2v.w;
    } else if (l == 30) {
        orow[120] = tv.x * inv + l2v.x;
    }
}

// ---------------- launcher ----------------------------------------------------------
extern "C" void kernel_launch(void* const* d_in, const int* in_sizes, int n_in,
                              void* d_out, int out_size)
{
    const float* x   = (const float*)d_in[0];
    const int*   ei  = (const int*)d_in[1];
    const float* w1l = (const float*)d_in[2];
    const float* b1  = (const float*)d_in[3];
    const float* w1r = (const float*)d_in[4];
    const float* wl1 = (const float*)d_in[5];
    const float* bl1 = (const float*)d_in[6];
    const float* w2l = (const float*)d_in[7];
    const float* b2  = (const float*)d_in[8];
    const float* w2r = (const float*)d_in[9];
    const float* wl2 = (const float*)d_in[10];
    const float* bl2 = (const float*)d_in[11];
    float* out = (float*)d_out;

    const int SMEM2 = (128 * SW + 2 * 192 * SW) * (int)sizeof(__half);          // 40960
    const int SMEM1 = (64 * ASW + 2 * 512 * SW) * (int)sizeof(__half)
                    + 64 * 4 * (int)sizeof(float);                              // 100352
    cudaFuncSetAttribute(gemm2_kernel,
                         cudaFuncAttributeMaxDynamicSharedMemorySize, SMEM2);
    cudaFuncSetAttribute(gemm1_kernel,
                         cudaFuncAttributeMaxDynamicSharedMemorySize, SMEM1);

    histsetup_kernel   <<<(NE + 255) / 256, 256>>>(ei, w1l, w1r, wl1, w2l, w2r, wl2); // 1
    offsets_kernel     <<<(NN + 1023) / 1024, 1024>>>();                              // 2
    fill_kernel        <<<(NE + 255) / 256, 256>>>(ei);                               // 3
    gather1_kernel     <<<(NNP * 32 + 255) / 256, 256>>>(x);                          // 4 <- profiled
    gemm1_kernel       <<<NNP / 64, 512, SMEM1>>>(b1, bl1);                           // 5
    gemm2_kernel       <<<(NNP / 128) * 2, 512, SMEM2>>>();                           // 6
    gather2_final_kernel<<<(NN * 32 + 255) / 256, 256>>>(b2, bl2, out);               // 7
}